// round 7
// baseline (speedup 1.0000x reference)
#include <cuda_runtime.h>
#include <math.h>

// Problem constants
#define NTOK 2048
#define CDIM 1024
#define NEXP 32
#define KSEL 4
#define HEXP 512
#define HSH  1024
#define NROW (NTOK * KSEL)   // 8192 grouped rows

// ---------------------------------------------------------------------------
// Static device scratch (no allocation allowed)
// ---------------------------------------------------------------------------
__device__ float g_U_sh[(size_t)NTOK * 2 * HSH];   // 16 MB  shared up-proj output
__device__ float g_S_sh[(size_t)NTOK * HSH];       // 8 MB   shared swiglu activation
__device__ float g_U_rt[(size_t)NROW * 2 * HEXP];  // 32 MB  routed up-proj output (grouped)
__device__ float g_S_rt[(size_t)NROW * HEXP];      // 16 MB  routed swiglu activation (pre-scaled)
__device__ float g_R[(size_t)NROW * CDIM];         // 32 MB  routed down-proj output (grouped)

__device__ int   g_topk_idx[NROW];
__device__ float g_topk_w[NROW];
__device__ int   g_counts[NEXP];
__device__ int   g_offsets[NEXP + 1];
__device__ int   g_cursor[NEXP];
__device__ int   g_tok_of_row[NROW];
__device__ float g_w_of_row[NROW];
__device__ int   g_rows_of_token[NROW];
__device__ int   g_plain_offsets[2] = {0, NTOK};

// ---------------------------------------------------------------------------
// Gating: one warp per token, lane = expert (E == 32)
// ---------------------------------------------------------------------------
__global__ void gate_kernel(const float* __restrict__ x,
                            const float* __restrict__ gw,
                            const float* __restrict__ gb)
{
    const int warp = threadIdx.x >> 5;
    const int lane = threadIdx.x & 31;
    const int n = blockIdx.x * 8 + warp;
    if (n >= NTOK) return;

    const float* xr = x + (size_t)n * CDIM;
    float acc = 0.f;
    #pragma unroll 4
    for (int c = 0; c < CDIM; ++c)
        acc += xr[c] * gw[c * NEXP + lane];   // xr[c] broadcast, gw coalesced

    const float score  = 1.f / (1.f + expf(-acc));
    float mb = score + gb[lane];              // biased score for selection only

    float wsum = 0.f;
    int   myIdx = 0;
    float myS   = 0.f;
    const float NEG_INF = __int_as_float(0xff800000);

    #pragma unroll
    for (int k = 0; k < KSEL; ++k) {
        float v = mb; int bi = lane;
        #pragma unroll
        for (int off = 16; off; off >>= 1) {
            float ov = __shfl_xor_sync(0xffffffffu, v, off);
            int   oi = __shfl_xor_sync(0xffffffffu, bi, off);
            if (ov > v || (ov == v && oi < bi)) { v = ov; bi = oi; }
        }
        float s = __shfl_sync(0xffffffffu, score, bi);
        wsum += s;
        if (lane == k)  { myIdx = bi; myS = s; }
        if (lane == bi) mb = NEG_INF;
    }

    if (lane < KSEL) {
        g_topk_idx[n * KSEL + lane] = myIdx;
        g_topk_w[n * KSEL + lane]   = myS / wsum;   // ROUTE_SCALE = 1.0
        atomicAdd(&g_counts[myIdx], 1);
    }
}

__global__ void reset_kernel()
{
    if (threadIdx.x < NEXP) g_counts[threadIdx.x] = 0;
}

__global__ void scan_kernel()
{
    if (threadIdx.x == 0) {
        int acc = 0;
        for (int e = 0; e < NEXP; ++e) {
            g_offsets[e] = acc;
            g_cursor[e]  = acc;
            acc += g_counts[e];
        }
        g_offsets[NEXP] = acc;   // == NROW
    }
}

__global__ void scatter_kernel()
{
    const int n = blockIdx.x * blockDim.x + threadIdx.x;
    if (n >= NTOK) return;
    #pragma unroll
    for (int k = 0; k < KSEL; ++k) {
        const int e = g_topk_idx[n * KSEL + k];
        const int pos = atomicAdd(&g_cursor[e], 1);
        g_tok_of_row[pos] = n;
        g_w_of_row[pos]   = g_topk_w[n * KSEL + k];
        g_rows_of_token[n * KSEL + k] = pos;
    }
}

// ---------------------------------------------------------------------------
// Tiled fp32 GEMM: C[rowBase+m, :] = A_row(m) @ B_e
// 128x128 tile, TK=16, 256 threads, 8x8 micro-tile, float4 paths.
// - offsets: per-"expert" row ranges in the grouped row space (grid.z = expert)
// - gather:  if non-null, A row index = gather[grouped_row] (token gather)
// - C rows are always grouped-row-contiguous (rowBase+m)
// ---------------------------------------------------------------------------
#define TM 128
#define TN 128
#define TKK 16

__global__ __launch_bounds__(256, 2)
void gemm_tiled(const float* __restrict__ A, int lda,
                const float* __restrict__ Bbase, long bStride, int ldb,
                float* __restrict__ Cbase, int ldc,
                int Kd,
                const int* __restrict__ offsets,
                const int* __restrict__ gather)
{
    __shared__ float As[TKK][TM + 4];
    __shared__ float Bs[TKK][TN];

    const int e = blockIdx.z;
    const int rowBase = offsets[e];
    const int Me = offsets[e + 1] - rowBase;
    const int tileM = blockIdx.y * TM;
    if (tileM >= Me) return;
    const int tileN = blockIdx.x * TN;
    const float* Bp = Bbase + (long)e * bStride;

    const int tid = threadIdx.x;
    const int tx = tid & 15;
    const int ty = tid >> 4;

    // A loader: covers 2 rows of the 128x16 A-tile per thread (as 1 float4 each)
    const int lr = tid >> 2;          // 0..63
    const int lk = (tid & 3) << 2;    // 0,4,8,12
    // B loader: covers 2 k-rows of the 16x128 B-tile per thread (as 1 float4 each)
    const int br = tid >> 5;          // 0..7
    const int bc = (tid & 31) << 2;   // 0..124

    // Hoist gathered A row pointers (k-invariant)
    const float* ap[2];
    bool av[2];
    #pragma unroll
    for (int i = 0; i < 2; ++i) {
        const int m = lr + i * 64;
        av[i] = (tileM + m) < Me;
        int ar = 0;
        if (av[i]) {
            const int gr = rowBase + tileM + m;
            ar = gather ? gather[gr] : gr;
        }
        ap[i] = A + (size_t)ar * lda;
    }

    float acc[8][8];
    #pragma unroll
    for (int i = 0; i < 8; ++i)
        #pragma unroll
        for (int j = 0; j < 8; ++j)
            acc[i][j] = 0.f;

    for (int k0 = 0; k0 < Kd; k0 += TKK) {
        // Load A tile (transposed into As[k][m])
        #pragma unroll
        for (int i = 0; i < 2; ++i) {
            const int m = lr + i * 64;
            float4 v = make_float4(0.f, 0.f, 0.f, 0.f);
            if (av[i]) v = *(const float4*)(ap[i] + k0 + lk);
            As[lk + 0][m] = v.x;
            As[lk + 1][m] = v.y;
            As[lk + 2][m] = v.z;
            As[lk + 3][m] = v.w;
        }
        // Load B tile (Bs[k][n])
        #pragma unroll
        for (int i = 0; i < 2; ++i) {
            const int kk = br + i * 8;
            *(float4*)&Bs[kk][bc] =
                *(const float4*)(Bp + (size_t)(k0 + kk) * ldb + tileN + bc);
        }
        __syncthreads();

        #pragma unroll
        for (int k = 0; k < TKK; ++k) {
            float a[8], b[8];
            *(float4*)&a[0] = *(const float4*)&As[k][ty * 8];
            *(float4*)&a[4] = *(const float4*)&As[k][ty * 8 + 4];
            *(float4*)&b[0] = *(const float4*)&Bs[k][tx * 8];
            *(float4*)&b[4] = *(const float4*)&Bs[k][tx * 8 + 4];
            #pragma unroll
            for (int i = 0; i < 8; ++i)
                #pragma unroll
                for (int j = 0; j < 8; ++j)
                    acc[i][j] += a[i] * b[j];
        }
        __syncthreads();
    }

    #pragma unroll
    for (int i = 0; i < 8; ++i) {
        const int m = tileM + ty * 8 + i;
        if (m < Me) {
            float* cp = Cbase + (size_t)(rowBase + m) * ldc + tileN + tx * 8;
            *(float4*)cp       = make_float4(acc[i][0], acc[i][1], acc[i][2], acc[i][3]);
            *(float4*)(cp + 4) = make_float4(acc[i][4], acc[i][5], acc[i][6], acc[i][7]);
        }
    }
}

// ---------------------------------------------------------------------------
// Elementwise SwiGLU
// ---------------------------------------------------------------------------
__device__ __forceinline__ float silu_f(float g) { return g / (1.f + expf(-g)); }

__global__ void swiglu_shared_kernel()   // grid = NTOK, 256 threads (HS/4 f4 each thread 1)
{
    const int row = blockIdx.x;
    const int t = threadIdx.x;
    const size_t base = (size_t)row * 2 * HSH;
    const float4 y = *(const float4*)&g_U_sh[base + t * 4];
    const float4 g = *(const float4*)&g_U_sh[base + HSH + t * 4];
    float4 s;
    s.x = y.x * silu_f(g.x);
    s.y = y.y * silu_f(g.y);
    s.z = y.z * silu_f(g.z);
    s.w = y.w * silu_f(g.w);
    *(float4*)&g_S_sh[(size_t)row * HSH + t * 4] = s;
}

__global__ void swiglu_routed_kernel()   // grid = NROW, 128 threads
{
    const int r = blockIdx.x;
    const int t = threadIdx.x;
    const float w = g_w_of_row[r];
    const size_t base = (size_t)r * 2 * HEXP;
    const float4 y = *(const float4*)&g_U_rt[base + t * 4];
    const float4 g = *(const float4*)&g_U_rt[base + HEXP + t * 4];
    float4 s;
    s.x = w * y.x * silu_f(g.x);
    s.y = w * y.y * silu_f(g.y);
    s.z = w * y.z * silu_f(g.z);
    s.w = w * y.w * silu_f(g.w);
    *(float4*)&g_S_rt[(size_t)r * HEXP + t * 4] = s;
}

// out[n] = shared(already in out) + sum_k R[rows_of_token[n][k]]
__global__ void combine_kernel(float* __restrict__ out)  // grid = NTOK, 256 threads
{
    const int n = blockIdx.x;
    const int t = threadIdx.x;
    const int r0 = g_rows_of_token[n * KSEL + 0];
    const int r1 = g_rows_of_token[n * KSEL + 1];
    const int r2 = g_rows_of_token[n * KSEL + 2];
    const int r3 = g_rows_of_token[n * KSEL + 3];

    float4 o  = *(float4*)&out[(size_t)n * CDIM + t * 4];
    const float4 a = *(const float4*)&g_R[(size_t)r0 * CDIM + t * 4];
    const float4 b = *(const float4*)&g_R[(size_t)r1 * CDIM + t * 4];
    const float4 c = *(const float4*)&g_R[(size_t)r2 * CDIM + t * 4];
    const float4 d = *(const float4*)&g_R[(size_t)r3 * CDIM + t * 4];
    o.x += a.x + b.x + c.x + d.x;
    o.y += a.y + b.y + c.y + d.y;
    o.z += a.z + b.z + c.z + d.z;
    o.w += a.w + b.w + c.w + d.w;
    *(float4*)&out[(size_t)n * CDIM + t * 4] = o;
}

// ---------------------------------------------------------------------------
// Launch
// ---------------------------------------------------------------------------
extern "C" void kernel_launch(void* const* d_in, const int* in_sizes, int n_in,
                              void* d_out, int out_size)
{
    (void)in_sizes; (void)n_in; (void)out_size;
    const float* x   = (const float*)d_in[0];   // (1,2048,1024)
    const float* gw  = (const float*)d_in[1];   // (1024,32)
    const float* gb  = (const float*)d_in[2];   // (32,)
    const float* sgw = (const float*)d_in[3];   // (1024,2048)
    const float* sdw = (const float*)d_in[4];   // (1024,1024)
    const float* egw = (const float*)d_in[5];   // (32,1024,1024)
    const float* edw = (const float*)d_in[6];   // (32,512,1024)
    float* out = (float*)d_out;

    // Resolve device-scratch addresses (no allocation, capture-safe)
    float *pU_sh, *pS_sh, *pU_rt, *pS_rt, *pR;
    int *pOffs, *pPlainOffs, *pTokOfRow;
    cudaGetSymbolAddress((void**)&pU_sh, g_U_sh);
    cudaGetSymbolAddress((void**)&pS_sh, g_S_sh);
    cudaGetSymbolAddress((void**)&pU_rt, g_U_rt);
    cudaGetSymbolAddress((void**)&pS_rt, g_S_rt);
    cudaGetSymbolAddress((void**)&pR,    g_R);
    cudaGetSymbolAddress((void**)&pOffs, g_offsets);
    cudaGetSymbolAddress((void**)&pPlainOffs, g_plain_offsets);
    cudaGetSymbolAddress((void**)&pTokOfRow, g_tok_of_row);

    // 1) routing
    reset_kernel<<<1, 64>>>();
    gate_kernel<<<NTOK / 8, 256>>>(x, gw, gb);
    scan_kernel<<<1, 32>>>();
    scatter_kernel<<<NTOK / 256, 256>>>();

    // 2) shared expert: U_sh = x @ sgw ; S_sh = swiglu(U_sh) ; out = S_sh @ sdw
    {
        dim3 grid(2 * HSH / TN, NTOK / TM, 1);
        gemm_tiled<<<grid, 256>>>(x, CDIM, sgw, 0, 2 * HSH,
                                  pU_sh, 2 * HSH, CDIM, pPlainOffs, nullptr);
    }
    swiglu_shared_kernel<<<NTOK, 256>>>();
    {
        dim3 grid(CDIM / TN, NTOK / TM, 1);
        gemm_tiled<<<grid, 256>>>(pS_sh, HSH, sdw, 0, CDIM,
                                  out, CDIM, HSH, pPlainOffs, nullptr);
    }

    // 3) routed experts (grouped): U_rt = gather(x) @ egw[e] ; S_rt = w * swiglu(U_rt)
    {
        dim3 grid(2 * HEXP / TN, NTOK / TM, NEXP);   // max Me = NTOK
        gemm_tiled<<<grid, 256>>>(x, CDIM, egw, (long)CDIM * 2 * HEXP, 2 * HEXP,
                                  pU_rt, 2 * HEXP, CDIM, pOffs, pTokOfRow);
    }
    swiglu_routed_kernel<<<NROW, 128>>>();
    // R = S_rt @ edw[e]   (grouped-contiguous rows)
    {
        dim3 grid(CDIM / TN, NTOK / TM, NEXP);
        gemm_tiled<<<grid, 256>>>(pS_rt, HEXP, edw, (long)HEXP * CDIM, CDIM,
                                  pR, CDIM, HEXP, pOffs, nullptr);
    }

    // 4) combine: out += sum of the 4 routed contributions per token
    combine_kernel<<<NTOK, 256>>>(out);
}

// round 8
// speedup vs baseline: 2.1739x; 2.1739x over previous
#include <cuda_runtime.h>
#include <math.h>

// Problem constants
#define NTOK 2048
#define CDIM 1024
#define NEXP 32
#define KSEL 4
#define HEXP 512
#define HSH  1024
#define NROW (NTOK * KSEL)   // 8192 grouped rows

// ---------------------------------------------------------------------------
// Static device scratch (no allocation allowed)
// ---------------------------------------------------------------------------
__device__ float g_U_sh[(size_t)NTOK * 2 * HSH];   // 16 MB  shared up-proj output
__device__ float g_S_sh[(size_t)NTOK * HSH];       // 8 MB   shared swiglu activation
__device__ float g_U_rt[(size_t)NROW * 2 * HEXP];  // 32 MB  routed up-proj output (grouped)
__device__ float g_S_rt[(size_t)NROW * HEXP];      // 16 MB  routed swiglu activation (pre-scaled)
__device__ float g_R[(size_t)NROW * CDIM];         // 32 MB  routed down-proj output (grouped)

__device__ int   g_topk_idx[NROW];
__device__ float g_topk_w[NROW];
__device__ int   g_counts[NEXP];
__device__ int   g_offsets[NEXP + 1];
__device__ int   g_cursor[NEXP];
__device__ int   g_tok_of_row[NROW];
__device__ float g_w_of_row[NROW];
__device__ int   g_rows_of_token[NROW];
__device__ int   g_plain_offsets[2] = {0, NTOK};

// ---------------------------------------------------------------------------
// Gating: one warp per token, lane = expert (E == 32)
// ---------------------------------------------------------------------------
__global__ void gate_kernel(const float* __restrict__ x,
                            const float* __restrict__ gw,
                            const float* __restrict__ gb)
{
    const int warp = threadIdx.x >> 5;
    const int lane = threadIdx.x & 31;
    const int n = blockIdx.x * 8 + warp;
    if (n >= NTOK) return;

    const float* xr = x + (size_t)n * CDIM;
    float acc = 0.f;
    #pragma unroll 4
    for (int c = 0; c < CDIM; ++c)
        acc += xr[c] * gw[c * NEXP + lane];   // xr[c] broadcast, gw coalesced

    const float score  = 1.f / (1.f + expf(-acc));
    float mb = score + gb[lane];              // biased score for selection only

    float wsum = 0.f;
    int   myIdx = 0;
    float myS   = 0.f;
    const float NEG_INF = __int_as_float(0xff800000);

    #pragma unroll
    for (int k = 0; k < KSEL; ++k) {
        float v = mb; int bi = lane;
        #pragma unroll
        for (int off = 16; off; off >>= 1) {
            float ov = __shfl_xor_sync(0xffffffffu, v, off);
            int   oi = __shfl_xor_sync(0xffffffffu, bi, off);
            if (ov > v || (ov == v && oi < bi)) { v = ov; bi = oi; }
        }
        float s = __shfl_sync(0xffffffffu, score, bi);
        wsum += s;
        if (lane == k)  { myIdx = bi; myS = s; }
        if (lane == bi) mb = NEG_INF;
    }

    if (lane < KSEL) {
        g_topk_idx[n * KSEL + lane] = myIdx;
        g_topk_w[n * KSEL + lane]   = myS / wsum;   // ROUTE_SCALE = 1.0
        atomicAdd(&g_counts[myIdx], 1);
    }
}

__global__ void reset_kernel()
{
    if (threadIdx.x < NEXP) g_counts[threadIdx.x] = 0;
}

__global__ void scan_kernel()
{
    if (threadIdx.x == 0) {
        int acc = 0;
        for (int e = 0; e < NEXP; ++e) {
            g_offsets[e] = acc;
            g_cursor[e]  = acc;
            acc += g_counts[e];
        }
        g_offsets[NEXP] = acc;   // == NROW
    }
}

__global__ void scatter_kernel()
{
    const int n = blockIdx.x * blockDim.x + threadIdx.x;
    if (n >= NTOK) return;
    #pragma unroll
    for (int k = 0; k < KSEL; ++k) {
        const int e = g_topk_idx[n * KSEL + k];
        const int pos = atomicAdd(&g_cursor[e], 1);
        g_tok_of_row[pos] = n;
        g_w_of_row[pos]   = g_topk_w[n * KSEL + k];
        g_rows_of_token[n * KSEL + k] = pos;
    }
}

// ---------------------------------------------------------------------------
// TF32 tensor-core GEMM: C[rowBase+m, :] = A_row(m) @ B_e
// 128x128x32 tile, 256 threads (8 warps, 2x4), warp tile 64x32,
// mma.sync.aligned.m16n8k8.row.col.f32.tf32.tf32.f32 (4x4 fragments/warp).
// - offsets: per-"expert" row ranges in the grouped row space (grid.z = expert)
// - gather:  if non-null, A row index = gather[grouped_row] (token gather)
// - C rows are always grouped-row-contiguous (rowBase+m)
// ---------------------------------------------------------------------------
#define KT 32
#define SMP 132   // smem row pitch (floats): 132*4 B = 528 B, 16B-aligned rows

__device__ __forceinline__ unsigned f2tf32(float f)
{
    unsigned u;
    asm("cvt.rna.tf32.f32 %0, %1;" : "=r"(u) : "f"(f));
    return u;
}

__device__ __forceinline__ void mma_tf32(float* c, const unsigned* a, const unsigned* b)
{
    asm volatile(
        "mma.sync.aligned.m16n8k8.row.col.f32.tf32.tf32.f32 "
        "{%0,%1,%2,%3}, {%4,%5,%6,%7}, {%8,%9}, {%0,%1,%2,%3};"
        : "+f"(c[0]), "+f"(c[1]), "+f"(c[2]), "+f"(c[3])
        : "r"(a[0]), "r"(a[1]), "r"(a[2]), "r"(a[3]),
          "r"(b[0]), "r"(b[1]));
}

__global__ __launch_bounds__(256)
void gemm_tf32(const float* __restrict__ A, int lda,
               const float* __restrict__ Bbase, long bStride, int ldb,
               float* __restrict__ Cbase, int ldc,
               int Kd,
               const int* __restrict__ offsets,
               const int* __restrict__ gather)
{
    __shared__ unsigned As[KT][SMP];   // [k][m]  (transposed)
    __shared__ unsigned Bs[KT][SMP];   // [k][n]

    const int e = blockIdx.z;
    const int rowBase = offsets[e];
    const int Me = offsets[e + 1] - rowBase;
    const int tileM = blockIdx.y * 128;
    if (tileM >= Me) return;
    const int tileN = blockIdx.x * 128;
    const float* Bp = Bbase + (long)e * bStride;

    const int tid  = threadIdx.x;
    const int wid  = tid >> 5;
    const int lane = tid & 31;
    const int g    = lane >> 2;        // groupID (0..7)
    const int tg   = lane & 3;         // thread-in-group (0..3)
    const int wm   = (wid & 1) * 64;   // warp m-offset within tile
    const int wn   = (wid >> 1) * 32;  // warp n-offset within tile

    // A loader: 4 iterations; each covers rows (tid>>3)+i*32, k-cols (tid&7)*4..+3
    const int ar = tid >> 3;           // 0..31
    const int ak = (tid & 7) * 4;      // 0,4,...,28
    const float* apt[4];
    bool av[4];
    #pragma unroll
    for (int i = 0; i < 4; ++i) {
        const int m = ar + i * 32;
        av[i] = (tileM + m) < Me;
        int arow = 0;
        if (av[i]) {
            const int gr = rowBase + tileM + m;
            arow = gather ? gather[gr] : gr;
        }
        apt[i] = A + (size_t)arow * lda;
    }

    // B loader: 4 iterations; k-row = wid + i*8, n-cols = lane*4..+3
    const int bn = lane * 4;

    float acc[4][4][4];
    #pragma unroll
    for (int mf = 0; mf < 4; ++mf)
        #pragma unroll
        for (int nf = 0; nf < 4; ++nf)
            #pragma unroll
            for (int r = 0; r < 4; ++r)
                acc[mf][nf][r] = 0.f;

    for (int k0 = 0; k0 < Kd; k0 += KT) {
        // ---- A tile: global -> tf32 -> smem transposed [k][m]
        #pragma unroll
        for (int i = 0; i < 4; ++i) {
            float4 v = make_float4(0.f, 0.f, 0.f, 0.f);
            if (av[i]) v = *(const float4*)(apt[i] + k0 + ak);
            const int m = ar + i * 32;
            As[ak + 0][m] = f2tf32(v.x);
            As[ak + 1][m] = f2tf32(v.y);
            As[ak + 2][m] = f2tf32(v.z);
            As[ak + 3][m] = f2tf32(v.w);
        }
        // ---- B tile: global -> tf32 -> smem [k][n]
        #pragma unroll
        for (int i = 0; i < 4; ++i) {
            const int kk = wid + i * 8;
            const float4 v = *(const float4*)(Bp + (size_t)(k0 + kk) * ldb + tileN + bn);
            uint4 u;
            u.x = f2tf32(v.x); u.y = f2tf32(v.y);
            u.z = f2tf32(v.z); u.w = f2tf32(v.w);
            *(uint4*)&Bs[kk][bn] = u;
        }
        __syncthreads();

        // ---- 4 k8-steps of m16n8k8 mma
        #pragma unroll
        for (int s = 0; s < 4; ++s) {
            const int kb = s * 8;
            unsigned a[4][4], b[4][2];
            #pragma unroll
            for (int mf = 0; mf < 4; ++mf) {
                const int m = wm + mf * 16 + g;
                a[mf][0] = As[kb + tg    ][m];
                a[mf][1] = As[kb + tg    ][m + 8];
                a[mf][2] = As[kb + tg + 4][m];
                a[mf][3] = As[kb + tg + 4][m + 8];
            }
            #pragma unroll
            for (int nf = 0; nf < 4; ++nf) {
                const int n = wn + nf * 8 + g;
                b[nf][0] = Bs[kb + tg    ][n];
                b[nf][1] = Bs[kb + tg + 4][n];
            }
            #pragma unroll
            for (int mf = 0; mf < 4; ++mf)
                #pragma unroll
                for (int nf = 0; nf < 4; ++nf)
                    mma_tf32(acc[mf][nf], a[mf], b[nf]);
        }
        __syncthreads();
    }

    // ---- Epilogue: c0,c1 at (row g, cols 2tg,2tg+1); c2,c3 at row g+8
    #pragma unroll
    for (int mf = 0; mf < 4; ++mf) {
        const int r0 = tileM + wm + mf * 16 + g;
        const int r1 = r0 + 8;
        #pragma unroll
        for (int nf = 0; nf < 4; ++nf) {
            const int col = tileN + wn + nf * 8 + tg * 2;
            if (r0 < Me)
                *(float2*)&Cbase[(size_t)(rowBase + r0) * ldc + col] =
                    make_float2(acc[mf][nf][0], acc[mf][nf][1]);
            if (r1 < Me)
                *(float2*)&Cbase[(size_t)(rowBase + r1) * ldc + col] =
                    make_float2(acc[mf][nf][2], acc[mf][nf][3]);
        }
    }
}

// ---------------------------------------------------------------------------
// Elementwise SwiGLU
// ---------------------------------------------------------------------------
__device__ __forceinline__ float silu_f(float g) { return g / (1.f + expf(-g)); }

__global__ void swiglu_shared_kernel()   // grid = NTOK, 256 threads
{
    const int row = blockIdx.x;
    const int t = threadIdx.x;
    const size_t base = (size_t)row * 2 * HSH;
    const float4 y = *(const float4*)&g_U_sh[base + t * 4];
    const float4 g = *(const float4*)&g_U_sh[base + HSH + t * 4];
    float4 s;
    s.x = y.x * silu_f(g.x);
    s.y = y.y * silu_f(g.y);
    s.z = y.z * silu_f(g.z);
    s.w = y.w * silu_f(g.w);
    *(float4*)&g_S_sh[(size_t)row * HSH + t * 4] = s;
}

__global__ void swiglu_routed_kernel()   // grid = NROW, 128 threads
{
    const int r = blockIdx.x;
    const int t = threadIdx.x;
    const float w = g_w_of_row[r];
    const size_t base = (size_t)r * 2 * HEXP;
    const float4 y = *(const float4*)&g_U_rt[base + t * 4];
    const float4 g = *(const float4*)&g_U_rt[base + HEXP + t * 4];
    float4 s;
    s.x = w * y.x * silu_f(g.x);
    s.y = w * y.y * silu_f(g.y);
    s.z = w * y.z * silu_f(g.z);
    s.w = w * y.w * silu_f(g.w);
    *(float4*)&g_S_rt[(size_t)r * HEXP + t * 4] = s;
}

// out[n] = shared(already in out) + sum_k R[rows_of_token[n][k]]
__global__ void combine_kernel(float* __restrict__ out)  // grid = NTOK, 256 threads
{
    const int n = blockIdx.x;
    const int t = threadIdx.x;
    const int r0 = g_rows_of_token[n * KSEL + 0];
    const int r1 = g_rows_of_token[n * KSEL + 1];
    const int r2 = g_rows_of_token[n * KSEL + 2];
    const int r3 = g_rows_of_token[n * KSEL + 3];

    float4 o  = *(float4*)&out[(size_t)n * CDIM + t * 4];
    const float4 a = *(const float4*)&g_R[(size_t)r0 * CDIM + t * 4];
    const float4 b = *(const float4*)&g_R[(size_t)r1 * CDIM + t * 4];
    const float4 c = *(const float4*)&g_R[(size_t)r2 * CDIM + t * 4];
    const float4 d = *(const float4*)&g_R[(size_t)r3 * CDIM + t * 4];
    o.x += a.x + b.x + c.x + d.x;
    o.y += a.y + b.y + c.y + d.y;
    o.z += a.z + b.z + c.z + d.z;
    o.w += a.w + b.w + c.w + d.w;
    *(float4*)&out[(size_t)n * CDIM + t * 4] = o;
}

// ---------------------------------------------------------------------------
// Launch
// ---------------------------------------------------------------------------
extern "C" void kernel_launch(void* const* d_in, const int* in_sizes, int n_in,
                              void* d_out, int out_size)
{
    (void)in_sizes; (void)n_in; (void)out_size;
    const float* x   = (const float*)d_in[0];   // (1,2048,1024)
    const float* gw  = (const float*)d_in[1];   // (1024,32)
    const float* gb  = (const float*)d_in[2];   // (32,)
    const float* sgw = (const float*)d_in[3];   // (1024,2048)
    const float* sdw = (const float*)d_in[4];   // (1024,1024)
    const float* egw = (const float*)d_in[5];   // (32,1024,1024)
    const float* edw = (const float*)d_in[6];   // (32,512,1024)
    float* out = (float*)d_out;

    // Resolve device-scratch addresses (no allocation, capture-safe)
    float *pU_sh, *pS_sh, *pU_rt, *pS_rt, *pR;
    int *pOffs, *pPlainOffs, *pTokOfRow;
    cudaGetSymbolAddress((void**)&pU_sh, g_U_sh);
    cudaGetSymbolAddress((void**)&pS_sh, g_S_sh);
    cudaGetSymbolAddress((void**)&pU_rt, g_U_rt);
    cudaGetSymbolAddress((void**)&pS_rt, g_S_rt);
    cudaGetSymbolAddress((void**)&pR,    g_R);
    cudaGetSymbolAddress((void**)&pOffs, g_offsets);
    cudaGetSymbolAddress((void**)&pPlainOffs, g_plain_offsets);
    cudaGetSymbolAddress((void**)&pTokOfRow, g_tok_of_row);

    // 1) routing
    reset_kernel<<<1, 64>>>();
    gate_kernel<<<NTOK / 8, 256>>>(x, gw, gb);
    scan_kernel<<<1, 32>>>();
    scatter_kernel<<<NTOK / 256, 256>>>();

    // 2) shared expert: U_sh = x @ sgw ; S_sh = swiglu(U_sh) ; out = S_sh @ sdw
    {
        dim3 grid(2 * HSH / 128, NTOK / 128, 1);
        gemm_tf32<<<grid, 256>>>(x, CDIM, sgw, 0, 2 * HSH,
                                 pU_sh, 2 * HSH, CDIM, pPlainOffs, nullptr);
    }
    swiglu_shared_kernel<<<NTOK, 256>>>();
    {
        dim3 grid(CDIM / 128, NTOK / 128, 1);
        gemm_tf32<<<grid, 256>>>(pS_sh, HSH, sdw, 0, CDIM,
                                 out, CDIM, HSH, pPlainOffs, nullptr);
    }

    // 3) routed experts (grouped): U_rt = gather(x) @ egw[e] ; S_rt = w * swiglu(U_rt)
    {
        dim3 grid(2 * HEXP / 128, NTOK / 128, NEXP);   // max Me = NTOK
        gemm_tf32<<<grid, 256>>>(x, CDIM, egw, (long)CDIM * 2 * HEXP, 2 * HEXP,
                                 pU_rt, 2 * HEXP, CDIM, pOffs, pTokOfRow);
    }
    swiglu_routed_kernel<<<NROW, 128>>>();
    // R = S_rt @ edw[e]   (grouped-contiguous rows)
    {
        dim3 grid(CDIM / 128, NTOK / 128, NEXP);
        gemm_tf32<<<grid, 256>>>(pS_rt, HEXP, edw, (long)HEXP * CDIM, CDIM,
                                 pR, CDIM, HEXP, pOffs, nullptr);
    }

    // 4) combine: out += sum of the 4 routed contributions per token
    combine_kernel<<<NTOK, 256>>>(out);
}

// round 12
// speedup vs baseline: 2.2381x; 1.0296x over previous
#include <cuda_runtime.h>
#include <math.h>

// Problem constants
#define NTOK 2048
#define CDIM 1024
#define NEXP 32
#define KSEL 4
#define HEXP 512
#define HSH  1024
#define NROW (NTOK * KSEL)   // 8192 grouped rows

// ---------------------------------------------------------------------------
// Static device scratch (no allocation allowed)
// ---------------------------------------------------------------------------
__device__ float g_U_sh[(size_t)NTOK * 2 * HSH];   // 16 MB  shared up-proj output
__device__ float g_S_sh[(size_t)NTOK * HSH];       // 8 MB   shared swiglu activation
__device__ float g_U_rt[(size_t)NROW * 2 * HEXP];  // 32 MB  routed up-proj output (grouped)
__device__ float g_S_rt[(size_t)NROW * HEXP];      // 16 MB  routed swiglu activation (pre-scaled)
__device__ float g_R[(size_t)NROW * CDIM];         // 32 MB  routed down-proj output (grouped)

__device__ int   g_topk_idx[NROW];
__device__ float g_topk_w[NROW];
__device__ int   g_counts[NEXP];
__device__ int   g_offsets[NEXP + 1];
__device__ int   g_cursor[NEXP];
__device__ int   g_tok_of_row[NROW];
__device__ float g_w_of_row[NROW];
__device__ int   g_rows_of_token[NROW];
__device__ int   g_plain_offsets[2] = {0, NTOK};

// ---------------------------------------------------------------------------
// Gating: one warp per token, lane = expert (E == 32)
// ---------------------------------------------------------------------------
__global__ void gate_kernel(const float* __restrict__ x,
                            const float* __restrict__ gw,
                            const float* __restrict__ gb)
{
    const int warp = threadIdx.x >> 5;
    const int lane = threadIdx.x & 31;
    const int n = blockIdx.x * 8 + warp;
    if (n >= NTOK) return;

    const float* xr = x + (size_t)n * CDIM;
    float acc = 0.f;
    #pragma unroll 4
    for (int c = 0; c < CDIM; ++c)
        acc += xr[c] * gw[c * NEXP + lane];   // xr[c] broadcast, gw coalesced

    const float score  = 1.f / (1.f + expf(-acc));
    float mb = score + gb[lane];              // biased score for selection only

    float wsum = 0.f;
    int   myIdx = 0;
    float myS   = 0.f;
    const float NEG_INF = __int_as_float(0xff800000);

    #pragma unroll
    for (int k = 0; k < KSEL; ++k) {
        float v = mb; int bi = lane;
        #pragma unroll
        for (int off = 16; off; off >>= 1) {
            float ov = __shfl_xor_sync(0xffffffffu, v, off);
            int   oi = __shfl_xor_sync(0xffffffffu, bi, off);
            if (ov > v || (ov == v && oi < bi)) { v = ov; bi = oi; }
        }
        float s = __shfl_sync(0xffffffffu, score, bi);
        wsum += s;
        if (lane == k)  { myIdx = bi; myS = s; }
        if (lane == bi) mb = NEG_INF;
    }

    if (lane < KSEL) {
        g_topk_idx[n * KSEL + lane] = myIdx;
        g_topk_w[n * KSEL + lane]   = myS / wsum;   // ROUTE_SCALE = 1.0
        atomicAdd(&g_counts[myIdx], 1);
    }
}

__global__ void reset_kernel()
{
    if (threadIdx.x < NEXP) g_counts[threadIdx.x] = 0;
}

__global__ void scan_kernel()
{
    if (threadIdx.x == 0) {
        int acc = 0;
        for (int e = 0; e < NEXP; ++e) {
            g_offsets[e] = acc;
            g_cursor[e]  = acc;
            acc += g_counts[e];
        }
        g_offsets[NEXP] = acc;   // == NROW
    }
}

__global__ void scatter_kernel()
{
    const int n = blockIdx.x * blockDim.x + threadIdx.x;
    if (n >= NTOK) return;
    #pragma unroll
    for (int k = 0; k < KSEL; ++k) {
        const int e = g_topk_idx[n * KSEL + k];
        const int pos = atomicAdd(&g_cursor[e], 1);
        g_tok_of_row[pos] = n;
        g_w_of_row[pos]   = g_topk_w[n * KSEL + k];
        g_rows_of_token[n * KSEL + k] = pos;
    }
}

// ---------------------------------------------------------------------------
// TF32 tensor-core GEMM, double-buffered, XOR-swizzled smem.
// Tile 128(M) x 256(N) x 16(K), 256 threads = 8 warps (2x4), warp tile 64x64.
// mma.sync.aligned.m16n8k8.row.col.f32.tf32.tf32.f32, 4x8 fragments per warp.
// Swizzle: phys_col = col ^ (8 * (k & 3))  -> conflict-free reads & writes.
// ---------------------------------------------------------------------------
#define BM 128
#define BN 256
#define KT 16

__device__ __forceinline__ unsigned f2tf32(float f)
{
    unsigned u;
    asm("cvt.rna.tf32.f32 %0, %1;" : "=r"(u) : "f"(f));
    return u;
}

__device__ __forceinline__ void mma_tf32(float* c, const unsigned* a, const unsigned* b)
{
    asm volatile(
        "mma.sync.aligned.m16n8k8.row.col.f32.tf32.tf32.f32 "
        "{%0,%1,%2,%3}, {%4,%5,%6,%7}, {%8,%9}, {%0,%1,%2,%3};"
        : "+f"(c[0]), "+f"(c[1]), "+f"(c[2]), "+f"(c[3])
        : "r"(a[0]), "r"(a[1]), "r"(a[2]), "r"(a[3]),
          "r"(b[0]), "r"(b[1]));
}

__global__ __launch_bounds__(256)
void gemm_tf32(const float* __restrict__ A, int lda,
               const float* __restrict__ Bbase, long bStride, int ldb,
               float* __restrict__ Cbase, int ldc,
               int Kd,
               const int* __restrict__ offsets,
               const int* __restrict__ gather)
{
    __shared__ unsigned As[2][KT][BM];   // [buf][k][m^swz]  16 KB
    __shared__ unsigned Bs[2][KT][BN];   // [buf][k][n^swz]  32 KB

    const int e = blockIdx.z;
    const int rowBase = offsets[e];
    const int Me = offsets[e + 1] - rowBase;
    const int tileM = blockIdx.y * BM;
    if (tileM >= Me) return;
    const int tileN = blockIdx.x * BN;
    const float* Bp = Bbase + (long)e * bStride;

    const int tid  = threadIdx.x;
    const int wid  = tid >> 5;
    const int lane = tid & 31;
    const int g    = lane >> 2;        // 0..7
    const int tg   = lane & 3;         // 0..3
    const int wm   = (wid & 1) * 64;   // warp m-offset
    const int wn   = (wid >> 1) * 64;  // warp n-offset
    const int swz  = tg * 8;           // fragment-read swizzle offset

    // ---- A loader: one m-row per thread, 8 k-values (2 float4 -> array, no aliasing)
    const int am  = tid >> 1;          // 0..127
    const int akh = (tid & 1) * 8;     // 0 or 8
    const bool av = (tileM + am) < Me;
    int arow = 0;
    if (av) {
        const int gr = rowBase + tileM + am;
        arow = gather ? gather[gr] : gr;
    }
    const float* apt = A + (size_t)arow * lda + akh;

    // ---- B loader: 4 float4 per thread (4 k-rows x 4 n-cols)
    const int bn4 = (tid & 63) * 4;    // 0..252
    const int bk0 = tid >> 6;          // 0..3
    const float* bpt = Bp + (size_t)bk0 * ldb + tileN + bn4;

    float aLoad[8];                    // contiguous staging (fix for UB aliasing)
    float4 breg[4];
    const float4 zf4 = make_float4(0.f, 0.f, 0.f, 0.f);

    // prologue: load tile 0
    *(float4*)&aLoad[0] = av ? *(const float4*)(apt)     : zf4;
    *(float4*)&aLoad[4] = av ? *(const float4*)(apt + 4) : zf4;
    #pragma unroll
    for (int i = 0; i < 4; ++i)
        breg[i] = *(const float4*)(bpt + (size_t)(i * 4) * ldb);

    // store tile 0 into buffer 0 (convert to tf32, swizzled)
    #pragma unroll
    for (int j = 0; j < 8; ++j) {
        const int kk = akh + j;
        As[0][kk][am ^ (8 * (kk & 3))] = f2tf32(aLoad[j]);
    }
    #pragma unroll
    for (int i = 0; i < 4; ++i) {
        const int kk = bk0 + i * 4;
        uint4 u;
        u.x = f2tf32(breg[i].x); u.y = f2tf32(breg[i].y);
        u.z = f2tf32(breg[i].z); u.w = f2tf32(breg[i].w);
        *(uint4*)&Bs[0][kk][bn4 ^ (8 * (kk & 3))] = u;
    }
    __syncthreads();

    float acc[4][8][4];
    #pragma unroll
    for (int mf = 0; mf < 4; ++mf)
        #pragma unroll
        for (int nf = 0; nf < 8; ++nf)
            #pragma unroll
            for (int r = 0; r < 4; ++r)
                acc[mf][nf][r] = 0.f;

    int buf = 0;
    for (int k0 = 0; k0 < Kd; k0 += KT) {
        const bool hasNext = (k0 + KT) < Kd;

        // issue next tile's global loads early (hidden behind MMA work)
        if (hasNext) {
            const float* ap2 = apt + k0 + KT;
            *(float4*)&aLoad[0] = av ? *(const float4*)(ap2)     : zf4;
            *(float4*)&aLoad[4] = av ? *(const float4*)(ap2 + 4) : zf4;
            const float* bp2 = bpt + (size_t)(k0 + KT) * ldb;
            #pragma unroll
            for (int i = 0; i < 4; ++i)
                breg[i] = *(const float4*)(bp2 + (size_t)(i * 4) * ldb);
        }

        // ---- compute on current buffer: 2 k8-steps
        #pragma unroll
        for (int s = 0; s < 2; ++s) {
            const int kb = s * 8;
            unsigned a[4][4], b[8][2];
            #pragma unroll
            for (int mf = 0; mf < 4; ++mf) {
                const int m = wm + mf * 16 + g;
                a[mf][0] = As[buf][kb + tg    ][ m      ^ swz];
                a[mf][1] = As[buf][kb + tg    ][(m + 8) ^ swz];
                a[mf][2] = As[buf][kb + tg + 4][ m      ^ swz];   // (tg+4)&3 == tg
                a[mf][3] = As[buf][kb + tg + 4][(m + 8) ^ swz];
            }
            #pragma unroll
            for (int nf = 0; nf < 8; ++nf) {
                const int n = wn + nf * 8 + g;
                b[nf][0] = Bs[buf][kb + tg    ][n ^ swz];
                b[nf][1] = Bs[buf][kb + tg + 4][n ^ swz];
            }
            #pragma unroll
            for (int mf = 0; mf < 4; ++mf)
                #pragma unroll
                for (int nf = 0; nf < 8; ++nf)
                    mma_tf32(acc[mf][nf], a[mf], b[nf]);
        }

        // ---- store next tile into the other buffer
        if (hasNext) {
            const int nb = buf ^ 1;
            #pragma unroll
            for (int j = 0; j < 8; ++j) {
                const int kk = akh + j;
                As[nb][kk][am ^ (8 * (kk & 3))] = f2tf32(aLoad[j]);
            }
            #pragma unroll
            for (int i = 0; i < 4; ++i) {
                const int kk = bk0 + i * 4;
                uint4 u;
                u.x = f2tf32(breg[i].x); u.y = f2tf32(breg[i].y);
                u.z = f2tf32(breg[i].z); u.w = f2tf32(breg[i].w);
                *(uint4*)&Bs[nb][kk][bn4 ^ (8 * (kk & 3))] = u;
            }
        }
        __syncthreads();
        buf ^= 1;
    }

    // ---- Epilogue: c0,c1 at (row g, cols 2tg,2tg+1); c2,c3 at row g+8
    #pragma unroll
    for (int mf = 0; mf < 4; ++mf) {
        const int r0 = tileM + wm + mf * 16 + g;
        const int r1 = r0 + 8;
        #pragma unroll
        for (int nf = 0; nf < 8; ++nf) {
            const int col = tileN + wn + nf * 8 + tg * 2;
            if (r0 < Me)
                *(float2*)&Cbase[(size_t)(rowBase + r0) * ldc + col] =
                    make_float2(acc[mf][nf][0], acc[mf][nf][1]);
            if (r1 < Me)
                *(float2*)&Cbase[(size_t)(rowBase + r1) * ldc + col] =
                    make_float2(acc[mf][nf][2], acc[mf][nf][3]);
        }
    }
}

// ---------------------------------------------------------------------------
// Elementwise SwiGLU
// ---------------------------------------------------------------------------
__device__ __forceinline__ float silu_f(float g) { return g / (1.f + expf(-g)); }

__global__ void swiglu_shared_kernel()   // grid = NTOK, 256 threads
{
    const int row = blockIdx.x;
    const int t = threadIdx.x;
    const size_t base = (size_t)row * 2 * HSH;
    const float4 y = *(const float4*)&g_U_sh[base + t * 4];
    const float4 g = *(const float4*)&g_U_sh[base + HSH + t * 4];
    float4 s;
    s.x = y.x * silu_f(g.x);
    s.y = y.y * silu_f(g.y);
    s.z = y.z * silu_f(g.z);
    s.w = y.w * silu_f(g.w);
    *(float4*)&g_S_sh[(size_t)row * HSH + t * 4] = s;
}

__global__ void swiglu_routed_kernel()   // grid = NROW, 128 threads
{
    const int r = blockIdx.x;
    const int t = threadIdx.x;
    const float w = g_w_of_row[r];
    const size_t base = (size_t)r * 2 * HEXP;
    const float4 y = *(const float4*)&g_U_rt[base + t * 4];
    const float4 g = *(const float4*)&g_U_rt[base + HEXP + t * 4];
    float4 s;
    s.x = w * y.x * silu_f(g.x);
    s.y = w * y.y * silu_f(g.y);
    s.z = w * y.z * silu_f(g.z);
    s.w = w * y.w * silu_f(g.w);
    *(float4*)&g_S_rt[(size_t)r * HEXP + t * 4] = s;
}

// out[n] = shared(already in out) + sum_k R[rows_of_token[n][k]]
__global__ void combine_kernel(float* __restrict__ out)  // grid = NTOK, 256 threads
{
    const int n = blockIdx.x;
    const int t = threadIdx.x;
    const int r0 = g_rows_of_token[n * KSEL + 0];
    const int r1 = g_rows_of_token[n * KSEL + 1];
    const int r2 = g_rows_of_token[n * KSEL + 2];
    const int r3 = g_rows_of_token[n * KSEL + 3];

    float4 o  = *(float4*)&out[(size_t)n * CDIM + t * 4];
    const float4 a = *(const float4*)&g_R[(size_t)r0 * CDIM + t * 4];
    const float4 b = *(const float4*)&g_R[(size_t)r1 * CDIM + t * 4];
    const float4 c = *(const float4*)&g_R[(size_t)r2 * CDIM + t * 4];
    const float4 d = *(const float4*)&g_R[(size_t)r3 * CDIM + t * 4];
    o.x += a.x + b.x + c.x + d.x;
    o.y += a.y + b.y + c.y + d.y;
    o.z += a.z + b.z + c.z + d.z;
    o.w += a.w + b.w + c.w + d.w;
    *(float4*)&out[(size_t)n * CDIM + t * 4] = o;
}

// ---------------------------------------------------------------------------
// Launch
// ---------------------------------------------------------------------------
extern "C" void kernel_launch(void* const* d_in, const int* in_sizes, int n_in,
                              void* d_out, int out_size)
{
    (void)in_sizes; (void)n_in; (void)out_size;
    const float* x   = (const float*)d_in[0];   // (1,2048,1024)
    const float* gw  = (const float*)d_in[1];   // (1024,32)
    const float* gb  = (const float*)d_in[2];   // (32,)
    const float* sgw = (const float*)d_in[3];   // (1024,2048)
    const float* sdw = (const float*)d_in[4];   // (1024,1024)
    const float* egw = (const float*)d_in[5];   // (32,1024,1024)
    const float* edw = (const float*)d_in[6];   // (32,512,1024)
    float* out = (float*)d_out;

    // Resolve device-scratch addresses (no allocation, capture-safe)
    float *pU_sh, *pS_sh, *pU_rt, *pS_rt, *pR;
    int *pOffs, *pPlainOffs, *pTokOfRow;
    cudaGetSymbolAddress((void**)&pU_sh, g_U_sh);
    cudaGetSymbolAddress((void**)&pS_sh, g_S_sh);
    cudaGetSymbolAddress((void**)&pU_rt, g_U_rt);
    cudaGetSymbolAddress((void**)&pS_rt, g_S_rt);
    cudaGetSymbolAddress((void**)&pR,    g_R);
    cudaGetSymbolAddress((void**)&pOffs, g_offsets);
    cudaGetSymbolAddress((void**)&pPlainOffs, g_plain_offsets);
    cudaGetSymbolAddress((void**)&pTokOfRow, g_tok_of_row);

    // 1) routing
    reset_kernel<<<1, 64>>>();
    gate_kernel<<<NTOK / 8, 256>>>(x, gw, gb);
    scan_kernel<<<1, 32>>>();
    scatter_kernel<<<NTOK / 256, 256>>>();

    // 2) shared expert: U_sh = x @ sgw ; S_sh = swiglu(U_sh) ; out = S_sh @ sdw
    {
        dim3 grid(2 * HSH / BN, NTOK / BM, 1);
        gemm_tf32<<<grid, 256>>>(x, CDIM, sgw, 0, 2 * HSH,
                                 pU_sh, 2 * HSH, CDIM, pPlainOffs, nullptr);
    }
    swiglu_shared_kernel<<<NTOK, 256>>>();
    {
        dim3 grid(CDIM / BN, NTOK / BM, 1);
        gemm_tf32<<<grid, 256>>>(pS_sh, HSH, sdw, 0, CDIM,
                                 out, CDIM, HSH, pPlainOffs, nullptr);
    }

    // 3) routed experts (grouped): U_rt = gather(x) @ egw[e] ; S_rt = w * swiglu(U_rt)
    {
        dim3 grid(2 * HEXP / BN, NTOK / BM, NEXP);   // max Me = NTOK
        gemm_tf32<<<grid, 256>>>(x, CDIM, egw, (long)CDIM * 2 * HEXP, 2 * HEXP,
                                 pU_rt, 2 * HEXP, CDIM, pOffs, pTokOfRow);
    }
    swiglu_routed_kernel<<<NROW, 128>>>();
    // R = S_rt @ edw[e]   (grouped-contiguous rows)
    {
        dim3 grid(CDIM / BN, NTOK / BM, NEXP);
        gemm_tf32<<<grid, 256>>>(pS_rt, HEXP, edw, (long)HEXP * CDIM, CDIM,
                                 pR, CDIM, HEXP, pOffs, nullptr);
    }

    // 4) combine: out += sum of the 4 routed contributions per token
    combine_kernel<<<NTOK, 256>>>(out);
}

// round 14
// speedup vs baseline: 2.9843x; 1.3334x over previous
#include <cuda_runtime.h>
#include <cuda_fp16.h>
#include <math.h>

// Problem constants
#define NTOK 2048
#define CDIM 1024
#define NEXP 32
#define KSEL 4
#define HEXP 512
#define HSH  1024
#define NROW (NTOK * KSEL)   // 8192 grouped rows

// ---------------------------------------------------------------------------
// Static device scratch (no allocation allowed)
// ---------------------------------------------------------------------------
__device__ float g_U_sh[(size_t)NTOK * 2 * HSH];   // 16 MB  shared up-proj output
__device__ float g_S_sh[(size_t)NTOK * HSH];       // 8 MB   shared swiglu activation
__device__ float g_U_rt[(size_t)NROW * 2 * HEXP];  // 32 MB  routed up-proj output (grouped)
__device__ float g_S_rt[(size_t)NROW * HEXP];      // 16 MB  routed swiglu activation (pre-scaled)
__device__ float g_R[(size_t)NROW * CDIM];         // 32 MB  routed down-proj output (grouped)

__device__ int   g_topk_idx[NROW];
__device__ float g_topk_w[NROW];
__device__ int   g_counts[NEXP];
__device__ int   g_offsets[NEXP + 1];
__device__ int   g_cursor[NEXP];
__device__ int   g_tok_of_row[NROW];
__device__ float g_w_of_row[NROW];
__device__ int   g_rows_of_token[NROW];
__device__ int   g_plain_offsets[2] = {0, NTOK};

// ---------------------------------------------------------------------------
// Gating: one warp per token, lane = expert (E == 32)
// ---------------------------------------------------------------------------
__global__ void gate_kernel(const float* __restrict__ x,
                            const float* __restrict__ gw,
                            const float* __restrict__ gb)
{
    const int warp = threadIdx.x >> 5;
    const int lane = threadIdx.x & 31;
    const int n = blockIdx.x * 8 + warp;
    if (n >= NTOK) return;

    const float* xr = x + (size_t)n * CDIM;
    float acc = 0.f;
    #pragma unroll 4
    for (int c = 0; c < CDIM; ++c)
        acc += xr[c] * gw[c * NEXP + lane];   // xr[c] broadcast, gw coalesced

    const float score  = 1.f / (1.f + expf(-acc));
    float mb = score + gb[lane];              // biased score for selection only

    float wsum = 0.f;
    int   myIdx = 0;
    float myS   = 0.f;
    const float NEG_INF = __int_as_float(0xff800000);

    #pragma unroll
    for (int k = 0; k < KSEL; ++k) {
        float v = mb; int bi = lane;
        #pragma unroll
        for (int off = 16; off; off >>= 1) {
            float ov = __shfl_xor_sync(0xffffffffu, v, off);
            int   oi = __shfl_xor_sync(0xffffffffu, bi, off);
            if (ov > v || (ov == v && oi < bi)) { v = ov; bi = oi; }
        }
        float s = __shfl_sync(0xffffffffu, score, bi);
        wsum += s;
        if (lane == k)  { myIdx = bi; myS = s; }
        if (lane == bi) mb = NEG_INF;
    }

    if (lane < KSEL) {
        g_topk_idx[n * KSEL + lane] = myIdx;
        g_topk_w[n * KSEL + lane]   = myS / wsum;   // ROUTE_SCALE = 1.0
        atomicAdd(&g_counts[myIdx], 1);
    }
}

__global__ void reset_kernel()
{
    if (threadIdx.x < NEXP) g_counts[threadIdx.x] = 0;
}

__global__ void scan_kernel()
{
    if (threadIdx.x == 0) {
        int acc = 0;
        for (int e = 0; e < NEXP; ++e) {
            g_offsets[e] = acc;
            g_cursor[e]  = acc;
            acc += g_counts[e];
        }
        g_offsets[NEXP] = acc;   // == NROW
    }
}

__global__ void scatter_kernel()
{
    const int n = blockIdx.x * blockDim.x + threadIdx.x;
    if (n >= NTOK) return;
    #pragma unroll
    for (int k = 0; k < KSEL; ++k) {
        const int e = g_topk_idx[n * KSEL + k];
        const int pos = atomicAdd(&g_cursor[e], 1);
        g_tok_of_row[pos] = n;
        g_w_of_row[pos]   = g_topk_w[n * KSEL + k];
        g_rows_of_token[n * KSEL + k] = pos;
    }
}

// ---------------------------------------------------------------------------
// FP16 tensor-core GEMM (fp32 accumulate), double-buffered, XOR-swizzled smem.
// Tile 128(M) x 256(N) x 32(K), 256 threads = 8 warps (2x4), warp tile 64x64.
// mma.sync.aligned.m16n8k16.row.col.f32.f16.f16.f32, 4x8 fragments per warp.
// Smem holds half2 k-pairs: As2[kp][m], Bs2[kp][n]; phys_col = col ^ (8*(kp&3)).
// ---------------------------------------------------------------------------
#define BM 128
#define BN 256
#define KT 32    // k floats per chunk
#define KP 16    // half2 pairs per chunk

__device__ __forceinline__ unsigned pack_h2(float lo, float hi)
{
    __half2 h = __floats2half2_rn(lo, hi);
    return *(unsigned*)&h;
}

__device__ __forceinline__ void mma_f16(float* c, const unsigned* a, const unsigned* b)
{
    asm volatile(
        "mma.sync.aligned.m16n8k16.row.col.f32.f16.f16.f32 "
        "{%0,%1,%2,%3}, {%4,%5,%6,%7}, {%8,%9}, {%0,%1,%2,%3};"
        : "+f"(c[0]), "+f"(c[1]), "+f"(c[2]), "+f"(c[3])
        : "r"(a[0]), "r"(a[1]), "r"(a[2]), "r"(a[3]),
          "r"(b[0]), "r"(b[1]));
}

__global__ __launch_bounds__(256)
void gemm_f16(const float* __restrict__ A, int lda,
              const float* __restrict__ Bbase, long bStride, int ldb,
              float* __restrict__ Cbase, int ldc,
              int Kd,
              const int* __restrict__ offsets,
              const int* __restrict__ gather)
{
    __shared__ unsigned As[2][KP][BM];   // 16 KB  (half2 pairs, [kp][m^swz])
    __shared__ unsigned Bs[2][KP][BN];   // 32 KB  (half2 pairs, [kp][n^swz])

    const int e = blockIdx.z;
    const int rowBase = offsets[e];
    const int Me = offsets[e + 1] - rowBase;
    const int tileM = blockIdx.y * BM;
    if (tileM >= Me) return;
    const int tileN = blockIdx.x * BN;
    const float* Bp = Bbase + (long)e * bStride;

    const int tid  = threadIdx.x;
    const int wid  = tid >> 5;
    const int lane = tid & 31;
    const int g    = lane >> 2;        // 0..7
    const int tg   = lane & 3;         // 0..3
    const int wm   = (wid & 1) * 64;   // warp m-offset
    const int wn   = (wid >> 1) * 64;  // warp n-offset
    const int swz  = tg * 8;           // fragment-read swizzle offset

    // ---- A loader: one m-row per thread, 16 consecutive k floats (4 float4)
    const int am  = tid & 127;         // m row within tile
    const int kh  = (tid >> 7) * 16;   // k float offset: 0 or 16
    const int kp0a = kh >> 1;          // first kp this thread fills: 0 or 8
    const bool av = (tileM + am) < Me;
    int arow = 0;
    if (av) {
        const int gr = rowBase + tileM + am;
        arow = gather ? gather[gr] : gr;
    }
    const float* apt = A + (size_t)arow * lda + kh;

    // ---- B loader: 4 kp rows x 4 n-cols per thread (2 float4 loads per kp)
    const int n4  = (tid & 63) * 4;    // 0..252
    const int kp0 = tid >> 6;          // 0..3
    const float* bpt = Bp + (size_t)(2 * kp0) * ldb + tileN + n4;

    float aLoad[16];
    float4 b0r[4], b1r[4];
    const float4 zf4 = make_float4(0.f, 0.f, 0.f, 0.f);

    // ---- prologue: load tile 0
    #pragma unroll
    for (int j = 0; j < 4; ++j)
        *(float4*)&aLoad[j * 4] = av ? *(const float4*)(apt + j * 4) : zf4;
    #pragma unroll
    for (int i = 0; i < 4; ++i) {
        b0r[i] = *(const float4*)(bpt + (size_t)(8 * i) * ldb);
        b1r[i] = *(const float4*)(bpt + (size_t)(8 * i + 1) * ldb);
    }

    // ---- store tile 0 into buffer 0
    #pragma unroll
    for (int j = 0; j < 8; ++j) {
        const int kp = kp0a + j;
        As[0][kp][am ^ (8 * (kp & 3))] = pack_h2(aLoad[2 * j], aLoad[2 * j + 1]);
    }
    #pragma unroll
    for (int i = 0; i < 4; ++i) {
        const int kp = kp0 + 4 * i;
        uint4 u;
        u.x = pack_h2(b0r[i].x, b1r[i].x);
        u.y = pack_h2(b0r[i].y, b1r[i].y);
        u.z = pack_h2(b0r[i].z, b1r[i].z);
        u.w = pack_h2(b0r[i].w, b1r[i].w);
        *(uint4*)&Bs[0][kp][n4 ^ (8 * (kp & 3))] = u;
    }
    __syncthreads();

    float acc[4][8][4];
    #pragma unroll
    for (int mf = 0; mf < 4; ++mf)
        #pragma unroll
        for (int nf = 0; nf < 8; ++nf)
            #pragma unroll
            for (int r = 0; r < 4; ++r)
                acc[mf][nf][r] = 0.f;

    int buf = 0;
    for (int k0 = 0; k0 < Kd; k0 += KT) {
        const bool hasNext = (k0 + KT) < Kd;

        // ---- issue next tile's global loads early (hidden behind MMA work)
        if (hasNext) {
            const float* ap2 = apt + k0 + KT;
            #pragma unroll
            for (int j = 0; j < 4; ++j)
                *(float4*)&aLoad[j * 4] = av ? *(const float4*)(ap2 + j * 4) : zf4;
            const float* bp2 = bpt + (size_t)(k0 + KT) * ldb;
            #pragma unroll
            for (int i = 0; i < 4; ++i) {
                b0r[i] = *(const float4*)(bp2 + (size_t)(8 * i) * ldb);
                b1r[i] = *(const float4*)(bp2 + (size_t)(8 * i + 1) * ldb);
            }
        }

        // ---- compute on current buffer: 2 k16-steps (pairs kb..kb+7)
        #pragma unroll
        for (int s = 0; s < 2; ++s) {
            const int kb = s * 8;
            unsigned a[4][4], b[8][2];
            #pragma unroll
            for (int mf = 0; mf < 4; ++mf) {
                const int m = wm + mf * 16 + g;
                a[mf][0] = As[buf][kb + tg    ][ m      ^ swz];
                a[mf][1] = As[buf][kb + tg    ][(m + 8) ^ swz];
                a[mf][2] = As[buf][kb + tg + 4][ m      ^ swz];   // (tg+4)&3 == tg
                a[mf][3] = As[buf][kb + tg + 4][(m + 8) ^ swz];
            }
            #pragma unroll
            for (int nf = 0; nf < 8; ++nf) {
                const int n = wn + nf * 8 + g;
                b[nf][0] = Bs[buf][kb + tg    ][n ^ swz];
                b[nf][1] = Bs[buf][kb + tg + 4][n ^ swz];
            }
            #pragma unroll
            for (int mf = 0; mf < 4; ++mf)
                #pragma unroll
                for (int nf = 0; nf < 8; ++nf)
                    mma_f16(acc[mf][nf], a[mf], b[nf]);
        }

        // ---- store next tile into the other buffer
        if (hasNext) {
            const int nb = buf ^ 1;
            #pragma unroll
            for (int j = 0; j < 8; ++j) {
                const int kp = kp0a + j;
                As[nb][kp][am ^ (8 * (kp & 3))] = pack_h2(aLoad[2 * j], aLoad[2 * j + 1]);
            }
            #pragma unroll
            for (int i = 0; i < 4; ++i) {
                const int kp = kp0 + 4 * i;
                uint4 u;
                u.x = pack_h2(b0r[i].x, b1r[i].x);
                u.y = pack_h2(b0r[i].y, b1r[i].y);
                u.z = pack_h2(b0r[i].z, b1r[i].z);
                u.w = pack_h2(b0r[i].w, b1r[i].w);
                *(uint4*)&Bs[nb][kp][n4 ^ (8 * (kp & 3))] = u;
            }
        }
        __syncthreads();
        buf ^= 1;
    }

    // ---- Epilogue: c0,c1 at (row g, cols 2tg,2tg+1); c2,c3 at row g+8
    #pragma unroll
    for (int mf = 0; mf < 4; ++mf) {
        const int r0 = tileM + wm + mf * 16 + g;
        const int r1 = r0 + 8;
        #pragma unroll
        for (int nf = 0; nf < 8; ++nf) {
            const int col = tileN + wn + nf * 8 + tg * 2;
            if (r0 < Me)
                *(float2*)&Cbase[(size_t)(rowBase + r0) * ldc + col] =
                    make_float2(acc[mf][nf][0], acc[mf][nf][1]);
            if (r1 < Me)
                *(float2*)&Cbase[(size_t)(rowBase + r1) * ldc + col] =
                    make_float2(acc[mf][nf][2], acc[mf][nf][3]);
        }
    }
}

// ---------------------------------------------------------------------------
// Elementwise SwiGLU
// ---------------------------------------------------------------------------
__device__ __forceinline__ float silu_f(float g) { return g / (1.f + expf(-g)); }

__global__ void swiglu_shared_kernel()   // grid = NTOK, 256 threads
{
    const int row = blockIdx.x;
    const int t = threadIdx.x;
    const size_t base = (size_t)row * 2 * HSH;
    const float4 y = *(const float4*)&g_U_sh[base + t * 4];
    const float4 g = *(const float4*)&g_U_sh[base + HSH + t * 4];
    float4 s;
    s.x = y.x * silu_f(g.x);
    s.y = y.y * silu_f(g.y);
    s.z = y.z * silu_f(g.z);
    s.w = y.w * silu_f(g.w);
    *(float4*)&g_S_sh[(size_t)row * HSH + t * 4] = s;
}

__global__ void swiglu_routed_kernel()   // grid = NROW, 128 threads
{
    const int r = blockIdx.x;
    const int t = threadIdx.x;
    const float w = g_w_of_row[r];
    const size_t base = (size_t)r * 2 * HEXP;
    const float4 y = *(const float4*)&g_U_rt[base + t * 4];
    const float4 g = *(const float4*)&g_U_rt[base + HEXP + t * 4];
    float4 s;
    s.x = w * y.x * silu_f(g.x);
    s.y = w * y.y * silu_f(g.y);
    s.z = w * y.z * silu_f(g.z);
    s.w = w * y.w * silu_f(g.w);
    *(float4*)&g_S_rt[(size_t)r * HEXP + t * 4] = s;
}

// out[n] = shared(already in out) + sum_k R[rows_of_token[n][k]]
__global__ void combine_kernel(float* __restrict__ out)  // grid = NTOK, 256 threads
{
    const int n = blockIdx.x;
    const int t = threadIdx.x;
    const int r0 = g_rows_of_token[n * KSEL + 0];
    const int r1 = g_rows_of_token[n * KSEL + 1];
    const int r2 = g_rows_of_token[n * KSEL + 2];
    const int r3 = g_rows_of_token[n * KSEL + 3];

    float4 o  = *(float4*)&out[(size_t)n * CDIM + t * 4];
    const float4 a = *(const float4*)&g_R[(size_t)r0 * CDIM + t * 4];
    const float4 b = *(const float4*)&g_R[(size_t)r1 * CDIM + t * 4];
    const float4 c = *(const float4*)&g_R[(size_t)r2 * CDIM + t * 4];
    const float4 d = *(const float4*)&g_R[(size_t)r3 * CDIM + t * 4];
    o.x += a.x + b.x + c.x + d.x;
    o.y += a.y + b.y + c.y + d.y;
    o.z += a.z + b.z + c.z + d.z;
    o.w += a.w + b.w + c.w + d.w;
    *(float4*)&out[(size_t)n * CDIM + t * 4] = o;
}

// ---------------------------------------------------------------------------
// Launch
// ---------------------------------------------------------------------------
extern "C" void kernel_launch(void* const* d_in, const int* in_sizes, int n_in,
                              void* d_out, int out_size)
{
    (void)in_sizes; (void)n_in; (void)out_size;
    const float* x   = (const float*)d_in[0];   // (1,2048,1024)
    const float* gw  = (const float*)d_in[1];   // (1024,32)
    const float* gb  = (const float*)d_in[2];   // (32,)
    const float* sgw = (const float*)d_in[3];   // (1024,2048)
    const float* sdw = (const float*)d_in[4];   // (1024,1024)
    const float* egw = (const float*)d_in[5];   // (32,1024,1024)
    const float* edw = (const float*)d_in[6];   // (32,512,1024)
    float* out = (float*)d_out;

    // Resolve device-scratch addresses (no allocation, capture-safe)
    float *pU_sh, *pS_sh, *pU_rt, *pS_rt, *pR;
    int *pOffs, *pPlainOffs, *pTokOfRow;
    cudaGetSymbolAddress((void**)&pU_sh, g_U_sh);
    cudaGetSymbolAddress((void**)&pS_sh, g_S_sh);
    cudaGetSymbolAddress((void**)&pU_rt, g_U_rt);
    cudaGetSymbolAddress((void**)&pS_rt, g_S_rt);
    cudaGetSymbolAddress((void**)&pR,    g_R);
    cudaGetSymbolAddress((void**)&pOffs, g_offsets);
    cudaGetSymbolAddress((void**)&pPlainOffs, g_plain_offsets);
    cudaGetSymbolAddress((void**)&pTokOfRow, g_tok_of_row);

    // 1) routing
    reset_kernel<<<1, 64>>>();
    gate_kernel<<<NTOK / 8, 256>>>(x, gw, gb);
    scan_kernel<<<1, 32>>>();
    scatter_kernel<<<NTOK / 256, 256>>>();

    // 2) shared expert: U_sh = x @ sgw ; S_sh = swiglu(U_sh) ; out = S_sh @ sdw
    {
        dim3 grid(2 * HSH / BN, NTOK / BM, 1);
        gemm_f16<<<grid, 256>>>(x, CDIM, sgw, 0, 2 * HSH,
                                pU_sh, 2 * HSH, CDIM, pPlainOffs, nullptr);
    }
    swiglu_shared_kernel<<<NTOK, 256>>>();
    {
        dim3 grid(CDIM / BN, NTOK / BM, 1);
        gemm_f16<<<grid, 256>>>(pS_sh, HSH, sdw, 0, CDIM,
                                out, CDIM, HSH, pPlainOffs, nullptr);
    }

    // 3) routed experts (grouped): U_rt = gather(x) @ egw[e] ; S_rt = w * swiglu(U_rt)
    {
        dim3 grid(2 * HEXP / BN, NTOK / BM, NEXP);   // max Me = NTOK
        gemm_f16<<<grid, 256>>>(x, CDIM, egw, (long)CDIM * 2 * HEXP, 2 * HEXP,
                                pU_rt, 2 * HEXP, CDIM, pOffs, pTokOfRow);
    }
    swiglu_routed_kernel<<<NROW, 128>>>();
    // R = S_rt @ edw[e]   (grouped-contiguous rows)
    {
        dim3 grid(CDIM / BN, NTOK / BM, NEXP);
        gemm_f16<<<grid, 256>>>(pS_rt, HEXP, edw, (long)HEXP * CDIM, CDIM,
                                pR, CDIM, HEXP, pOffs, nullptr);
    }

    // 4) combine: out += sum of the 4 routed contributions per token
    combine_kernel<<<NTOK, 256>>>(out);
}

// round 15
// speedup vs baseline: 3.5783x; 1.1990x over previous
#include <cuda_runtime.h>
#include <cuda_fp16.h>
#include <math.h>

// Problem constants
#define NTOK 2048
#define CDIM 1024
#define NEXP 32
#define KSEL 4
#define HEXP 512
#define HSH  1024
#define NROW (NTOK * KSEL)   // 8192 grouped rows

#define BM 128
#define BN 256
#define KT 32    // k floats per chunk
#define KP 16    // half2 pairs per chunk

// ---------------------------------------------------------------------------
// Static device scratch (no allocation allowed)
// ---------------------------------------------------------------------------
__device__ float g_U_sh[(size_t)NTOK * 2 * HSH];   // shared up-proj output
__device__ float g_S_sh[(size_t)NTOK * HSH];       // shared swiglu activation
__device__ float g_U_rt[(size_t)NROW * 2 * HEXP];  // routed up-proj output (grouped)
__device__ float g_S_rt[(size_t)NROW * HEXP];      // routed swiglu activation (pre-scaled)
__device__ float g_R[(size_t)NROW * CDIM];         // routed down-proj output (grouped)

__device__ int   g_topk_idx[NROW];
__device__ float g_topk_w[NROW];
__device__ int   g_counts[NEXP];
__device__ int   g_offsets[NEXP + 1];
__device__ int   g_cursor[NEXP];
__device__ int   g_mtile_base[NEXP + 1];   // cumulative M-tiles per expert
__device__ int   g_tile_ctr[2];            // dynamic tile counters (UP, DOWN)
__device__ int   g_tok_of_row[NROW];
__device__ float g_w_of_row[NROW];
__device__ int   g_rows_of_token[NROW];

// ---------------------------------------------------------------------------
// Gating: one warp per token, lane = expert (E == 32)
// ---------------------------------------------------------------------------
__global__ void gate_kernel(const float* __restrict__ x,
                            const float* __restrict__ gw,
                            const float* __restrict__ gb)
{
    const int warp = threadIdx.x >> 5;
    const int lane = threadIdx.x & 31;
    const int n = blockIdx.x * 8 + warp;
    if (n >= NTOK) return;

    const float* xr = x + (size_t)n * CDIM;
    float acc = 0.f;
    #pragma unroll 4
    for (int c = 0; c < CDIM; ++c)
        acc += xr[c] * gw[c * NEXP + lane];

    const float score  = 1.f / (1.f + expf(-acc));
    float mb = score + gb[lane];

    float wsum = 0.f;
    int   myIdx = 0;
    float myS   = 0.f;
    const float NEG_INF = __int_as_float(0xff800000);

    #pragma unroll
    for (int k = 0; k < KSEL; ++k) {
        float v = mb; int bi = lane;
        #pragma unroll
        for (int off = 16; off; off >>= 1) {
            float ov = __shfl_xor_sync(0xffffffffu, v, off);
            int   oi = __shfl_xor_sync(0xffffffffu, bi, off);
            if (ov > v || (ov == v && oi < bi)) { v = ov; bi = oi; }
        }
        float s = __shfl_sync(0xffffffffu, score, bi);
        wsum += s;
        if (lane == k)  { myIdx = bi; myS = s; }
        if (lane == bi) mb = NEG_INF;
    }

    if (lane < KSEL) {
        g_topk_idx[n * KSEL + lane] = myIdx;
        g_topk_w[n * KSEL + lane]   = myS / wsum;   // ROUTE_SCALE = 1.0
        atomicAdd(&g_counts[myIdx], 1);
    }
}

__global__ void reset_kernel()
{
    if (threadIdx.x < NEXP) g_counts[threadIdx.x] = 0;
}

__global__ void scan_kernel()
{
    if (threadIdx.x == 0) {
        int acc = 0, mt = 0;
        for (int e = 0; e < NEXP; ++e) {
            g_offsets[e] = acc;
            g_cursor[e]  = acc;
            g_mtile_base[e] = mt;
            const int cnt = g_counts[e];
            acc += cnt;
            mt  += (cnt + BM - 1) / BM;
        }
        g_offsets[NEXP] = acc;     // == NROW
        g_mtile_base[NEXP] = mt;
        g_tile_ctr[0] = 0;
        g_tile_ctr[1] = 0;
    }
}

__global__ void scatter_kernel()
{
    const int n = blockIdx.x * blockDim.x + threadIdx.x;
    if (n >= NTOK) return;
    #pragma unroll
    for (int k = 0; k < KSEL; ++k) {
        const int e = g_topk_idx[n * KSEL + k];
        const int pos = atomicAdd(&g_cursor[e], 1);
        g_tok_of_row[pos] = n;
        g_w_of_row[pos]   = g_topk_w[n * KSEL + k];
        g_rows_of_token[n * KSEL + k] = pos;
    }
}

// ---------------------------------------------------------------------------
// FP16 tensor-core GEMM tile (fp32 accumulate), double-buffered, XOR-swizzled.
// Tile 128(M) x 256(N) x 32(K chunk), 256 threads = 8 warps (2x4), warp 64x64.
// Byte-identical mainloop to the proven R14 kernel, as an inlined function.
// ---------------------------------------------------------------------------
struct SmemT {
    unsigned As[2][KP][BM];   // 16 KB (half2 pairs, [kp][m^swz])
    unsigned Bs[2][KP][BN];   // 32 KB (half2 pairs, [kp][n^swz])
};

__device__ __forceinline__ unsigned pack_h2(float lo, float hi)
{
    __half2 h = __floats2half2_rn(lo, hi);
    return *(unsigned*)&h;
}

__device__ __forceinline__ void mma_f16(float* c, const unsigned* a, const unsigned* b)
{
    asm volatile(
        "mma.sync.aligned.m16n8k16.row.col.f32.f16.f16.f32 "
        "{%0,%1,%2,%3}, {%4,%5,%6,%7}, {%8,%9}, {%0,%1,%2,%3};"
        : "+f"(c[0]), "+f"(c[1]), "+f"(c[2]), "+f"(c[3])
        : "r"(a[0]), "r"(a[1]), "r"(a[2]), "r"(a[3]),
          "r"(b[0]), "r"(b[1]));
}

__device__ __forceinline__ void run_tile(SmemT& SMEM,
    const float* __restrict__ A, int lda,
    const float* __restrict__ Bp, int ldb,
    float* __restrict__ Cbase, int ldc, int Kd,
    int rowBase, int Me, int tileM, int tileN,
    const int* __restrict__ gather)
{
    const int tid  = threadIdx.x;
    const int wid  = tid >> 5;
    const int lane = tid & 31;
    const int g    = lane >> 2;        // 0..7
    const int tg   = lane & 3;         // 0..3
    const int wm   = (wid & 1) * 64;   // warp m-offset
    const int wn   = (wid >> 1) * 64;  // warp n-offset
    const int swz  = tg * 8;           // fragment-read swizzle offset

    // ---- A loader: one m-row per thread, 16 consecutive k floats
    const int am  = tid & 127;
    const int kh  = (tid >> 7) * 16;   // 0 or 16
    const int kp0a = kh >> 1;          // 0 or 8
    const bool av = (tileM + am) < Me;
    int arow = 0;
    if (av) {
        const int gr = rowBase + tileM + am;
        arow = gather ? gather[gr] : gr;
    }
    const float* apt = A + (size_t)arow * lda + kh;

    // ---- B loader: 4 kp rows x 4 n-cols per thread
    const int n4  = (tid & 63) * 4;    // 0..252
    const int kp0 = tid >> 6;          // 0..3
    const float* bpt = Bp + (size_t)(2 * kp0) * ldb + tileN + n4;

    float aLoad[16];
    float4 b0r[4], b1r[4];
    const float4 zf4 = make_float4(0.f, 0.f, 0.f, 0.f);

    // ---- prologue: load tile 0
    #pragma unroll
    for (int j = 0; j < 4; ++j)
        *(float4*)&aLoad[j * 4] = av ? *(const float4*)(apt + j * 4) : zf4;
    #pragma unroll
    for (int i = 0; i < 4; ++i) {
        b0r[i] = *(const float4*)(bpt + (size_t)(8 * i) * ldb);
        b1r[i] = *(const float4*)(bpt + (size_t)(8 * i + 1) * ldb);
    }

    // ---- store tile 0 into buffer 0
    #pragma unroll
    for (int j = 0; j < 8; ++j) {
        const int kp = kp0a + j;
        SMEM.As[0][kp][am ^ (8 * (kp & 3))] = pack_h2(aLoad[2 * j], aLoad[2 * j + 1]);
    }
    #pragma unroll
    for (int i = 0; i < 4; ++i) {
        const int kp = kp0 + 4 * i;
        uint4 u;
        u.x = pack_h2(b0r[i].x, b1r[i].x);
        u.y = pack_h2(b0r[i].y, b1r[i].y);
        u.z = pack_h2(b0r[i].z, b1r[i].z);
        u.w = pack_h2(b0r[i].w, b1r[i].w);
        *(uint4*)&SMEM.Bs[0][kp][n4 ^ (8 * (kp & 3))] = u;
    }
    __syncthreads();

    float acc[4][8][4];
    #pragma unroll
    for (int mf = 0; mf < 4; ++mf)
        #pragma unroll
        for (int nf = 0; nf < 8; ++nf)
            #pragma unroll
            for (int r = 0; r < 4; ++r)
                acc[mf][nf][r] = 0.f;

    int buf = 0;
    for (int k0 = 0; k0 < Kd; k0 += KT) {
        const bool hasNext = (k0 + KT) < Kd;

        if (hasNext) {
            const float* ap2 = apt + k0 + KT;
            #pragma unroll
            for (int j = 0; j < 4; ++j)
                *(float4*)&aLoad[j * 4] = av ? *(const float4*)(ap2 + j * 4) : zf4;
            const float* bp2 = bpt + (size_t)(k0 + KT) * ldb;
            #pragma unroll
            for (int i = 0; i < 4; ++i) {
                b0r[i] = *(const float4*)(bp2 + (size_t)(8 * i) * ldb);
                b1r[i] = *(const float4*)(bp2 + (size_t)(8 * i + 1) * ldb);
            }
        }

        #pragma unroll
        for (int s = 0; s < 2; ++s) {
            const int kb = s * 8;
            unsigned a[4][4], b[8][2];
            #pragma unroll
            for (int mf = 0; mf < 4; ++mf) {
                const int m = wm + mf * 16 + g;
                a[mf][0] = SMEM.As[buf][kb + tg    ][ m      ^ swz];
                a[mf][1] = SMEM.As[buf][kb + tg    ][(m + 8) ^ swz];
                a[mf][2] = SMEM.As[buf][kb + tg + 4][ m      ^ swz];   // (tg+4)&3 == tg
                a[mf][3] = SMEM.As[buf][kb + tg + 4][(m + 8) ^ swz];
            }
            #pragma unroll
            for (int nf = 0; nf < 8; ++nf) {
                const int n = wn + nf * 8 + g;
                b[nf][0] = SMEM.Bs[buf][kb + tg    ][n ^ swz];
                b[nf][1] = SMEM.Bs[buf][kb + tg + 4][n ^ swz];
            }
            #pragma unroll
            for (int mf = 0; mf < 4; ++mf)
                #pragma unroll
                for (int nf = 0; nf < 8; ++nf)
                    mma_f16(acc[mf][nf], a[mf], b[nf]);
        }

        if (hasNext) {
            const int nb = buf ^ 1;
            #pragma unroll
            for (int j = 0; j < 8; ++j) {
                const int kp = kp0a + j;
                SMEM.As[nb][kp][am ^ (8 * (kp & 3))] = pack_h2(aLoad[2 * j], aLoad[2 * j + 1]);
            }
            #pragma unroll
            for (int i = 0; i < 4; ++i) {
                const int kp = kp0 + 4 * i;
                uint4 u;
                u.x = pack_h2(b0r[i].x, b1r[i].x);
                u.y = pack_h2(b0r[i].y, b1r[i].y);
                u.z = pack_h2(b0r[i].z, b1r[i].z);
                u.w = pack_h2(b0r[i].w, b1r[i].w);
                *(uint4*)&SMEM.Bs[nb][kp][n4 ^ (8 * (kp & 3))] = u;
            }
        }
        __syncthreads();
        buf ^= 1;
    }

    // ---- Epilogue
    #pragma unroll
    for (int mf = 0; mf < 4; ++mf) {
        const int r0 = tileM + wm + mf * 16 + g;
        const int r1 = r0 + 8;
        #pragma unroll
        for (int nf = 0; nf < 8; ++nf) {
            const int col = tileN + wn + nf * 8 + tg * 2;
            if (r0 < Me)
                *(float2*)&Cbase[(size_t)(rowBase + r0) * ldc + col] =
                    make_float2(acc[mf][nf][0], acc[mf][nf][1]);
            if (r1 < Me)
                *(float2*)&Cbase[(size_t)(rowBase + r1) * ldc + col] =
                    make_float2(acc[mf][nf][2], acc[mf][nf][3]);
        }
    }
}

// ---------------------------------------------------------------------------
// Persistent merged GEMM: segment S (shared/plain, tiles first) + segment R
// (routed/grouped). Blocks pull tiles from a global atomic counter.
// ---------------------------------------------------------------------------
__global__ __launch_bounds__(256)
void gemm_moe(int which,
              const float* __restrict__ A_s, int lda_s,
              const float* __restrict__ B_s, int ldb_s,
              float* __restrict__ C_s, int ldc_s, int Kd_s, int mt_s, int ntN_s,
              const float* __restrict__ A_r, int lda_r,
              const float* __restrict__ B_r, long bStr_r, int ldb_r,
              float* __restrict__ C_r, int ldc_r, int Kd_r, int ntN_r,
              const int* __restrict__ gather)
{
    __shared__ SmemT SMEM;
    __shared__ int s_t;
    __shared__ int s_mtb[NEXP + 1];
    __shared__ int s_off[NEXP + 1];

    if (threadIdx.x <= NEXP) {
        s_mtb[threadIdx.x] = g_mtile_base[threadIdx.x];
        s_off[threadIdx.x] = g_offsets[threadIdx.x];
    }
    __syncthreads();

    const int T_s = mt_s * ntN_s;
    const int T   = T_s + s_mtb[NEXP] * ntN_r;

    for (;;) {
        if (threadIdx.x == 0) s_t = atomicAdd(&g_tile_ctr[which], 1);
        __syncthreads();
        const int t = s_t;
        __syncthreads();
        if (t >= T) break;

        const float *A, *Bp;
        float* C;
        int lda, ldb, ldc, Kd, rowBase, Me, tileM, tileN;
        const int* gth;

        if (t < T_s) {
            const int mt = t / ntN_s;
            const int nt = t - mt * ntN_s;
            A = A_s; lda = lda_s; Bp = B_s; ldb = ldb_s;
            C = C_s; ldc = ldc_s; Kd = Kd_s;
            rowBase = 0; Me = NTOK;
            tileM = mt * BM; tileN = nt * BN;
            gth = nullptr;
        } else {
            const int tt = t - T_s;
            const int mt = tt / ntN_r;
            const int nt = tt - mt * ntN_r;
            int e = 0;
            while (s_mtb[e + 1] <= mt) ++e;
            A = A_r; lda = lda_r;
            Bp = B_r + (long)e * bStr_r; ldb = ldb_r;
            C = C_r; ldc = ldc_r; Kd = Kd_r;
            rowBase = s_off[e]; Me = s_off[e + 1] - rowBase;
            tileM = (mt - s_mtb[e]) * BM; tileN = nt * BN;
            gth = gather;
        }

        run_tile(SMEM, A, lda, Bp, ldb, C, ldc, Kd, rowBase, Me, tileM, tileN, gth);
    }
}

// ---------------------------------------------------------------------------
// Merged elementwise SwiGLU (shared rows first, then routed rows)
// ---------------------------------------------------------------------------
__device__ __forceinline__ float silu_f(float g) { return g / (1.f + expf(-g)); }

__global__ void swiglu_all()   // grid = NTOK + NROW, 256 threads
{
    const int b = blockIdx.x;
    const int t = threadIdx.x;
    if (b < NTOK) {
        const size_t base = (size_t)b * 2 * HSH;
        const float4 y = *(const float4*)&g_U_sh[base + t * 4];
        const float4 g = *(const float4*)&g_U_sh[base + HSH + t * 4];
        float4 s;
        s.x = y.x * silu_f(g.x);
        s.y = y.y * silu_f(g.y);
        s.z = y.z * silu_f(g.z);
        s.w = y.w * silu_f(g.w);
        *(float4*)&g_S_sh[(size_t)b * HSH + t * 4] = s;
    } else if (t < 128) {
        const int r = b - NTOK;
        const float w = g_w_of_row[r];
        const size_t base = (size_t)r * 2 * HEXP;
        const float4 y = *(const float4*)&g_U_rt[base + t * 4];
        const float4 g = *(const float4*)&g_U_rt[base + HEXP + t * 4];
        float4 s;
        s.x = w * y.x * silu_f(g.x);
        s.y = w * y.y * silu_f(g.y);
        s.z = w * y.z * silu_f(g.z);
        s.w = w * y.w * silu_f(g.w);
        *(float4*)&g_S_rt[(size_t)r * HEXP + t * 4] = s;
    }
}

// out[n] = shared(already in out) + sum_k R[rows_of_token[n][k]]
__global__ void combine_kernel(float* __restrict__ out)  // grid = NTOK, 256 threads
{
    const int n = blockIdx.x;
    const int t = threadIdx.x;
    const int r0 = g_rows_of_token[n * KSEL + 0];
    const int r1 = g_rows_of_token[n * KSEL + 1];
    const int r2 = g_rows_of_token[n * KSEL + 2];
    const int r3 = g_rows_of_token[n * KSEL + 3];

    float4 o  = *(float4*)&out[(size_t)n * CDIM + t * 4];
    const float4 a = *(const float4*)&g_R[(size_t)r0 * CDIM + t * 4];
    const float4 b = *(const float4*)&g_R[(size_t)r1 * CDIM + t * 4];
    const float4 c = *(const float4*)&g_R[(size_t)r2 * CDIM + t * 4];
    const float4 d = *(const float4*)&g_R[(size_t)r3 * CDIM + t * 4];
    o.x += a.x + b.x + c.x + d.x;
    o.y += a.y + b.y + c.y + d.y;
    o.z += a.z + b.z + c.z + d.z;
    o.w += a.w + b.w + c.w + d.w;
    *(float4*)&out[(size_t)n * CDIM + t * 4] = o;
}

// ---------------------------------------------------------------------------
// Launch
// ---------------------------------------------------------------------------
extern "C" void kernel_launch(void* const* d_in, const int* in_sizes, int n_in,
                              void* d_out, int out_size)
{
    (void)in_sizes; (void)n_in; (void)out_size;
    const float* x   = (const float*)d_in[0];   // (1,2048,1024)
    const float* gw  = (const float*)d_in[1];   // (1024,32)
    const float* gb  = (const float*)d_in[2];   // (32,)
    const float* sgw = (const float*)d_in[3];   // (1024,2048)
    const float* sdw = (const float*)d_in[4];   // (1024,1024)
    const float* egw = (const float*)d_in[5];   // (32,1024,1024)
    const float* edw = (const float*)d_in[6];   // (32,512,1024)
    float* out = (float*)d_out;

    // Resolve device-scratch addresses (no allocation, capture-safe)
    float *pU_sh, *pS_sh, *pU_rt, *pS_rt, *pR;
    int *pTokOfRow;
    cudaGetSymbolAddress((void**)&pU_sh, g_U_sh);
    cudaGetSymbolAddress((void**)&pS_sh, g_S_sh);
    cudaGetSymbolAddress((void**)&pU_rt, g_U_rt);
    cudaGetSymbolAddress((void**)&pS_rt, g_S_rt);
    cudaGetSymbolAddress((void**)&pR,    g_R);
    cudaGetSymbolAddress((void**)&pTokOfRow, g_tok_of_row);

    int nsm = 148;
    cudaDeviceGetAttribute(&nsm, cudaDevAttrMultiProcessorCount, 0);

    // 1) routing
    reset_kernel<<<1, 64>>>();
    gate_kernel<<<NTOK / 8, 256>>>(x, gw, gb);
    scan_kernel<<<1, 32>>>();
    scatter_kernel<<<NTOK / 256, 256>>>();

    // 2) UP: merged persistent GEMM (shared-up segment + routed-up segment)
    gemm_moe<<<nsm, 256>>>(0,
        x, CDIM, sgw, 2 * HSH, pU_sh, 2 * HSH, CDIM, NTOK / BM, 2 * HSH / BN,
        x, CDIM, egw, (long)CDIM * 2 * HEXP, 2 * HEXP,
        pU_rt, 2 * HEXP, CDIM, 2 * HEXP / BN, pTokOfRow);

    // 3) SwiGLU (both paths in one launch)
    swiglu_all<<<NTOK + NROW, 256>>>();

    // 4) DOWN: merged persistent GEMM (shared-down heavy tiles first + routed-down)
    gemm_moe<<<nsm, 256>>>(1,
        pS_sh, HSH, sdw, CDIM, out, CDIM, HSH, NTOK / BM, CDIM / BN,
        pS_rt, HEXP, edw, (long)HEXP * CDIM, CDIM,
        pR, CDIM, HEXP, CDIM / BN, nullptr);

    // 5) combine
    combine_kernel<<<NTOK, 256>>>(out);
}

// round 16
// speedup vs baseline: 4.1293x; 1.1540x over previous
#include <cuda_runtime.h>
#include <cuda_fp16.h>
#include <math.h>

// Problem constants
#define NTOK 2048
#define CDIM 1024
#define NEXP 32
#define KSEL 4
#define HEXP 512
#define HSH  1024
#define NROW (NTOK * KSEL)   // 8192 grouped rows

#define BM 128
#define BN 256
#define KT 32    // k floats per chunk
#define KP 16    // half2 pairs per chunk

// ---------------------------------------------------------------------------
// Static device scratch (no allocation allowed)
// ---------------------------------------------------------------------------
__device__ float g_S_sh[(size_t)NTOK * HSH];       // shared swiglu activation
__device__ float g_S_rt[(size_t)NROW * HEXP];      // routed swiglu activation (pre-scaled)
__device__ float g_R[(size_t)NROW * CDIM];         // routed down-proj output (grouped)

__device__ int   g_topk_idx[NROW];
__device__ float g_topk_w[NROW];
__device__ int   g_counts[NEXP];
__device__ int   g_offsets[NEXP + 1];
__device__ int   g_cursor[NEXP];
__device__ int   g_mtile_base[NEXP + 1];   // cumulative M-tiles per expert
__device__ int   g_tile_ctr[2];            // dynamic tile counters (UP, DOWN)
__device__ int   g_tok_of_row[NROW];
__device__ float g_w_of_row[NROW];
__device__ int   g_rows_of_token[NROW];

// ---------------------------------------------------------------------------
// Gating: one warp per token, lane = expert (E == 32)
// ---------------------------------------------------------------------------
__global__ void gate_kernel(const float* __restrict__ x,
                            const float* __restrict__ gw,
                            const float* __restrict__ gb)
{
    const int warp = threadIdx.x >> 5;
    const int lane = threadIdx.x & 31;
    const int n = blockIdx.x * 8 + warp;
    if (n >= NTOK) return;

    const float* xr = x + (size_t)n * CDIM;
    float acc = 0.f;
    #pragma unroll 2
    for (int c = 0; c < CDIM; c += 4) {
        const float4 xv = *(const float4*)(xr + c);
        acc += xv.x * gw[(c + 0) * NEXP + lane]
             + xv.y * gw[(c + 1) * NEXP + lane]
             + xv.z * gw[(c + 2) * NEXP + lane]
             + xv.w * gw[(c + 3) * NEXP + lane];
    }

    const float score  = 1.f / (1.f + expf(-acc));
    float mb = score + gb[lane];

    float wsum = 0.f;
    int   myIdx = 0;
    float myS   = 0.f;
    const float NEG_INF = __int_as_float(0xff800000);

    #pragma unroll
    for (int k = 0; k < KSEL; ++k) {
        float v = mb; int bi = lane;
        #pragma unroll
        for (int off = 16; off; off >>= 1) {
            float ov = __shfl_xor_sync(0xffffffffu, v, off);
            int   oi = __shfl_xor_sync(0xffffffffu, bi, off);
            if (ov > v || (ov == v && oi < bi)) { v = ov; bi = oi; }
        }
        float s = __shfl_sync(0xffffffffu, score, bi);
        wsum += s;
        if (lane == k)  { myIdx = bi; myS = s; }
        if (lane == bi) mb = NEG_INF;
    }

    if (lane < KSEL) {
        g_topk_idx[n * KSEL + lane] = myIdx;
        g_topk_w[n * KSEL + lane]   = myS / wsum;   // ROUTE_SCALE = 1.0
        atomicAdd(&g_counts[myIdx], 1);
    }
}

__global__ void reset_kernel()
{
    if (threadIdx.x < NEXP) g_counts[threadIdx.x] = 0;
}

__global__ void scan_kernel()
{
    if (threadIdx.x == 0) {
        int acc = 0, mt = 0;
        for (int e = 0; e < NEXP; ++e) {
            g_offsets[e] = acc;
            g_cursor[e]  = acc;
            g_mtile_base[e] = mt;
            const int cnt = g_counts[e];
            acc += cnt;
            mt  += (cnt + BM - 1) / BM;
        }
        g_offsets[NEXP] = acc;     // == NROW
        g_mtile_base[NEXP] = mt;
        g_tile_ctr[0] = 0;
        g_tile_ctr[1] = 0;
    }
}

__global__ void scatter_kernel()
{
    const int n = blockIdx.x * blockDim.x + threadIdx.x;
    if (n >= NTOK) return;
    #pragma unroll
    for (int k = 0; k < KSEL; ++k) {
        const int e = g_topk_idx[n * KSEL + k];
        const int pos = atomicAdd(&g_cursor[e], 1);
        g_tok_of_row[pos] = n;
        g_w_of_row[pos]   = g_topk_w[n * KSEL + k];
        g_rows_of_token[n * KSEL + k] = pos;
    }
}

// ---------------------------------------------------------------------------
// FP16 tensor-core GEMM tile (fp32 accumulate), double-buffered, XOR-swizzled.
// Tile 128(M) x 256(N) x 32(K chunk), 256 threads = 8 warps (2x4), warp 64x64.
// FUSE=true: B columns loaded interleaved (phys 2c = y_c, 2c+1 = g_c), and the
// epilogue writes S[row][c] = w * y * silu(g)  (fused SwiGLU, no U roundtrip).
// ---------------------------------------------------------------------------
struct SmemT {
    unsigned As[2][KP][BM];   // 16 KB (half2 pairs, [kp][m^swz])
    unsigned Bs[2][KP][BN];   // 32 KB (half2 pairs, [kp][n^swz])
};

__device__ __forceinline__ unsigned pack_h2(float lo, float hi)
{
    __half2 h = __floats2half2_rn(lo, hi);
    return *(unsigned*)&h;
}

__device__ __forceinline__ void mma_f16(float* c, const unsigned* a, const unsigned* b)
{
    asm volatile(
        "mma.sync.aligned.m16n8k16.row.col.f32.f16.f16.f32 "
        "{%0,%1,%2,%3}, {%4,%5,%6,%7}, {%8,%9}, {%0,%1,%2,%3};"
        : "+f"(c[0]), "+f"(c[1]), "+f"(c[2]), "+f"(c[3])
        : "r"(a[0]), "r"(a[1]), "r"(a[2]), "r"(a[3]),
          "r"(b[0]), "r"(b[1]));
}

__device__ __forceinline__ float silu_f(float g) { return g / (1.f + expf(-g)); }

template<bool FUSE>
__device__ __forceinline__ void run_tile(SmemT& SMEM,
    const float* __restrict__ A, int lda,
    const float* __restrict__ Bp, int ldb,
    float* __restrict__ Cbase, int ldc, int Kd,
    int rowBase, int Me, int tileM, int tileN,
    const int* __restrict__ gather,
    const float* __restrict__ wrow)     // per-row scale (FUSE routed) or null
{
    const int tid  = threadIdx.x;
    const int wid  = tid >> 5;
    const int lane = tid & 31;
    const int g    = lane >> 2;        // 0..7
    const int tg   = lane & 3;         // 0..3
    const int wm   = (wid & 1) * 64;   // warp m-offset
    const int wn   = (wid >> 1) * 64;  // warp n-offset
    const int swz  = tg * 8;           // fragment-read swizzle offset

    // ---- A loader: one m-row per thread, 16 consecutive k floats
    const int am  = tid & 127;
    const int kh  = (tid >> 7) * 16;   // 0 or 16
    const int kp0a = kh >> 1;          // 0 or 8
    const bool av = (tileM + am) < Me;
    int arow = 0;
    if (av) {
        const int gr = rowBase + tileM + am;
        arow = gather ? gather[gr] : gr;
    }
    const float* apt = A + (size_t)arow * lda + kh;

    // ---- B loader: 4 kp rows x 4 phys n-cols per thread
    const int n4  = (tid & 63) * 4;    // 0..252 (phys col)
    const int kp0 = tid >> 6;          // 0..3
    // plain: contiguous float4 at tileN+n4
    const float* bpt = Bp + (size_t)(2 * kp0) * ldb + tileN + n4;
    // fused: two float2 streams, y at col c, g at col c + ldb/2
    const int hc = (tileN + n4) >> 1;  // logical y/g column
    const float* byp = Bp + (size_t)(2 * kp0) * ldb + hc;
    const float* bgp = byp + (ldb >> 1);

    float aLoad[16];
    float4 b0r[4], b1r[4];
    const float4 zf4 = make_float4(0.f, 0.f, 0.f, 0.f);

    // ---- prologue: load tile 0
    #pragma unroll
    for (int j = 0; j < 4; ++j)
        *(float4*)&aLoad[j * 4] = av ? *(const float4*)(apt + j * 4) : zf4;
    #pragma unroll
    for (int i = 0; i < 4; ++i) {
        if (FUSE) {
            const float2 y0 = *(const float2*)(byp + (size_t)(8 * i) * ldb);
            const float2 g0 = *(const float2*)(bgp + (size_t)(8 * i) * ldb);
            const float2 y1 = *(const float2*)(byp + (size_t)(8 * i + 1) * ldb);
            const float2 g1 = *(const float2*)(bgp + (size_t)(8 * i + 1) * ldb);
            b0r[i] = make_float4(y0.x, g0.x, y0.y, g0.y);
            b1r[i] = make_float4(y1.x, g1.x, y1.y, g1.y);
        } else {
            b0r[i] = *(const float4*)(bpt + (size_t)(8 * i) * ldb);
            b1r[i] = *(const float4*)(bpt + (size_t)(8 * i + 1) * ldb);
        }
    }

    // ---- store tile 0 into buffer 0
    #pragma unroll
    for (int j = 0; j < 8; ++j) {
        const int kp = kp0a + j;
        SMEM.As[0][kp][am ^ (8 * (kp & 3))] = pack_h2(aLoad[2 * j], aLoad[2 * j + 1]);
    }
    #pragma unroll
    for (int i = 0; i < 4; ++i) {
        const int kp = kp0 + 4 * i;
        uint4 u;
        u.x = pack_h2(b0r[i].x, b1r[i].x);
        u.y = pack_h2(b0r[i].y, b1r[i].y);
        u.z = pack_h2(b0r[i].z, b1r[i].z);
        u.w = pack_h2(b0r[i].w, b1r[i].w);
        *(uint4*)&SMEM.Bs[0][kp][n4 ^ (8 * (kp & 3))] = u;
    }
    __syncthreads();

    float acc[4][8][4];
    #pragma unroll
    for (int mf = 0; mf < 4; ++mf)
        #pragma unroll
        for (int nf = 0; nf < 8; ++nf)
            #pragma unroll
            for (int r = 0; r < 4; ++r)
                acc[mf][nf][r] = 0.f;

    int buf = 0;
    for (int k0 = 0; k0 < Kd; k0 += KT) {
        const bool hasNext = (k0 + KT) < Kd;

        if (hasNext) {
            const float* ap2 = apt + k0 + KT;
            #pragma unroll
            for (int j = 0; j < 4; ++j)
                *(float4*)&aLoad[j * 4] = av ? *(const float4*)(ap2 + j * 4) : zf4;
            #pragma unroll
            for (int i = 0; i < 4; ++i) {
                if (FUSE) {
                    const float* by2 = byp + (size_t)(k0 + KT) * ldb;
                    const float* bg2 = bgp + (size_t)(k0 + KT) * ldb;
                    const float2 y0 = *(const float2*)(by2 + (size_t)(8 * i) * ldb);
                    const float2 g0 = *(const float2*)(bg2 + (size_t)(8 * i) * ldb);
                    const float2 y1 = *(const float2*)(by2 + (size_t)(8 * i + 1) * ldb);
                    const float2 g1 = *(const float2*)(bg2 + (size_t)(8 * i + 1) * ldb);
                    b0r[i] = make_float4(y0.x, g0.x, y0.y, g0.y);
                    b1r[i] = make_float4(y1.x, g1.x, y1.y, g1.y);
                } else {
                    const float* bp2 = bpt + (size_t)(k0 + KT) * ldb;
                    b0r[i] = *(const float4*)(bp2 + (size_t)(8 * i) * ldb);
                    b1r[i] = *(const float4*)(bp2 + (size_t)(8 * i + 1) * ldb);
                }
            }
        }

        #pragma unroll
        for (int s = 0; s < 2; ++s) {
            const int kb = s * 8;
            unsigned a[4][4], b[8][2];
            #pragma unroll
            for (int mf = 0; mf < 4; ++mf) {
                const int m = wm + mf * 16 + g;
                a[mf][0] = SMEM.As[buf][kb + tg    ][ m      ^ swz];
                a[mf][1] = SMEM.As[buf][kb + tg    ][(m + 8) ^ swz];
                a[mf][2] = SMEM.As[buf][kb + tg + 4][ m      ^ swz];   // (tg+4)&3 == tg
                a[mf][3] = SMEM.As[buf][kb + tg + 4][(m + 8) ^ swz];
            }
            #pragma unroll
            for (int nf = 0; nf < 8; ++nf) {
                const int n = wn + nf * 8 + g;
                b[nf][0] = SMEM.Bs[buf][kb + tg    ][n ^ swz];
                b[nf][1] = SMEM.Bs[buf][kb + tg + 4][n ^ swz];
            }
            #pragma unroll
            for (int mf = 0; mf < 4; ++mf)
                #pragma unroll
                for (int nf = 0; nf < 8; ++nf)
                    mma_f16(acc[mf][nf], a[mf], b[nf]);
        }

        if (hasNext) {
            const int nb = buf ^ 1;
            #pragma unroll
            for (int j = 0; j < 8; ++j) {
                const int kp = kp0a + j;
                SMEM.As[nb][kp][am ^ (8 * (kp & 3))] = pack_h2(aLoad[2 * j], aLoad[2 * j + 1]);
            }
            #pragma unroll
            for (int i = 0; i < 4; ++i) {
                const int kp = kp0 + 4 * i;
                uint4 u;
                u.x = pack_h2(b0r[i].x, b1r[i].x);
                u.y = pack_h2(b0r[i].y, b1r[i].y);
                u.z = pack_h2(b0r[i].z, b1r[i].z);
                u.w = pack_h2(b0r[i].w, b1r[i].w);
                *(uint4*)&SMEM.Bs[nb][kp][n4 ^ (8 * (kp & 3))] = u;
            }
        }
        __syncthreads();
        buf ^= 1;
    }

    // ---- Epilogue
    if (FUSE) {
        // acc[..][0] = y, acc[..][1] = g at phys col pc; S col = (tileN+pc)/2
        #pragma unroll
        for (int mf = 0; mf < 4; ++mf) {
            const int r0 = tileM + wm + mf * 16 + g;
            const int r1 = r0 + 8;
            float w0 = 1.f, w1 = 1.f;
            if (wrow) {
                if (r0 < Me) w0 = wrow[rowBase + r0];
                if (r1 < Me) w1 = wrow[rowBase + r1];
            }
            #pragma unroll
            for (int nf = 0; nf < 8; ++nf) {
                const int pc = wn + nf * 8 + tg * 2;
                const int oc = (tileN + pc) >> 1;
                if (r0 < Me)
                    Cbase[(size_t)(rowBase + r0) * ldc + oc] =
                        w0 * acc[mf][nf][0] * silu_f(acc[mf][nf][1]);
                if (r1 < Me)
                    Cbase[(size_t)(rowBase + r1) * ldc + oc] =
                        w1 * acc[mf][nf][2] * silu_f(acc[mf][nf][3]);
            }
        }
    } else {
        #pragma unroll
        for (int mf = 0; mf < 4; ++mf) {
            const int r0 = tileM + wm + mf * 16 + g;
            const int r1 = r0 + 8;
            #pragma unroll
            for (int nf = 0; nf < 8; ++nf) {
                const int col = tileN + wn + nf * 8 + tg * 2;
                if (r0 < Me)
                    *(float2*)&Cbase[(size_t)(rowBase + r0) * ldc + col] =
                        make_float2(acc[mf][nf][0], acc[mf][nf][1]);
                if (r1 < Me)
                    *(float2*)&Cbase[(size_t)(rowBase + r1) * ldc + col] =
                        make_float2(acc[mf][nf][2], acc[mf][nf][3]);
            }
        }
    }
}

// ---------------------------------------------------------------------------
// Persistent merged GEMM: segment S (shared/plain) + segment R (routed/grouped).
// Blocks pull tiles from a global atomic counter. FUSE selects swiglu epilogue.
// ---------------------------------------------------------------------------
template<bool FUSE>
__global__ __launch_bounds__(256)
void gemm_moe(int which,
              const float* __restrict__ A_s, int lda_s,
              const float* __restrict__ B_s, int ldb_s,
              float* __restrict__ C_s, int ldc_s, int Kd_s, int mt_s, int ntN_s,
              const float* __restrict__ A_r, int lda_r,
              const float* __restrict__ B_r, long bStr_r, int ldb_r,
              float* __restrict__ C_r, int ldc_r, int Kd_r, int ntN_r,
              const int* __restrict__ gather,
              const float* __restrict__ wrow_r)
{
    __shared__ SmemT SMEM;
    __shared__ int s_t;
    __shared__ int s_mtb[NEXP + 1];
    __shared__ int s_off[NEXP + 1];

    if (threadIdx.x <= NEXP) {
        s_mtb[threadIdx.x] = g_mtile_base[threadIdx.x];
        s_off[threadIdx.x] = g_offsets[threadIdx.x];
    }
    __syncthreads();

    const int T_s = mt_s * ntN_s;
    const int T   = T_s + s_mtb[NEXP] * ntN_r;

    for (;;) {
        if (threadIdx.x == 0) s_t = atomicAdd(&g_tile_ctr[which], 1);
        __syncthreads();
        const int t = s_t;
        __syncthreads();
        if (t >= T) break;

        if (t < T_s) {
            const int mt = t / ntN_s;
            const int nt = t - mt * ntN_s;
            run_tile<FUSE>(SMEM, A_s, lda_s, B_s, ldb_s, C_s, ldc_s, Kd_s,
                           0, NTOK, mt * BM, nt * BN, nullptr, nullptr);
        } else {
            const int tt = t - T_s;
            const int mt = tt / ntN_r;
            const int nt = tt - mt * ntN_r;
            int e = 0;
            while (s_mtb[e + 1] <= mt) ++e;
            run_tile<FUSE>(SMEM, A_r, lda_r, B_r + (long)e * bStr_r, ldb_r,
                           C_r, ldc_r, Kd_r,
                           s_off[e], s_off[e + 1] - s_off[e],
                           (mt - s_mtb[e]) * BM, nt * BN, gather, wrow_r);
        }
    }
}

// out[n] = shared(already in out) + sum_k R[rows_of_token[n][k]]
__global__ void combine_kernel(float* __restrict__ out)  // grid = NTOK, 256 threads
{
    const int n = blockIdx.x;
    const int t = threadIdx.x;
    const int r0 = g_rows_of_token[n * KSEL + 0];
    const int r1 = g_rows_of_token[n * KSEL + 1];
    const int r2 = g_rows_of_token[n * KSEL + 2];
    const int r3 = g_rows_of_token[n * KSEL + 3];

    float4 o  = *(float4*)&out[(size_t)n * CDIM + t * 4];
    const float4 a = *(const float4*)&g_R[(size_t)r0 * CDIM + t * 4];
    const float4 b = *(const float4*)&g_R[(size_t)r1 * CDIM + t * 4];
    const float4 c = *(const float4*)&g_R[(size_t)r2 * CDIM + t * 4];
    const float4 d = *(const float4*)&g_R[(size_t)r3 * CDIM + t * 4];
    o.x += a.x + b.x + c.x + d.x;
    o.y += a.y + b.y + c.y + d.y;
    o.z += a.z + b.z + c.z + d.z;
    o.w += a.w + b.w + c.w + d.w;
    *(float4*)&out[(size_t)n * CDIM + t * 4] = o;
}

// ---------------------------------------------------------------------------
// Launch
// ---------------------------------------------------------------------------
extern "C" void kernel_launch(void* const* d_in, const int* in_sizes, int n_in,
                              void* d_out, int out_size)
{
    (void)in_sizes; (void)n_in; (void)out_size;
    const float* x   = (const float*)d_in[0];   // (1,2048,1024)
    const float* gw  = (const float*)d_in[1];   // (1024,32)
    const float* gb  = (const float*)d_in[2];   // (32,)
    const float* sgw = (const float*)d_in[3];   // (1024,2048)
    const float* sdw = (const float*)d_in[4];   // (1024,1024)
    const float* egw = (const float*)d_in[5];   // (32,1024,1024)
    const float* edw = (const float*)d_in[6];   // (32,512,1024)
    float* out = (float*)d_out;

    // Resolve device-scratch addresses (no allocation, capture-safe)
    float *pS_sh, *pS_rt, *pR, *pWrow;
    int *pTokOfRow;
    cudaGetSymbolAddress((void**)&pS_sh, g_S_sh);
    cudaGetSymbolAddress((void**)&pS_rt, g_S_rt);
    cudaGetSymbolAddress((void**)&pR,    g_R);
    cudaGetSymbolAddress((void**)&pWrow, g_w_of_row);
    cudaGetSymbolAddress((void**)&pTokOfRow, g_tok_of_row);

    int nsm = 148;
    cudaDeviceGetAttribute(&nsm, cudaDevAttrMultiProcessorCount, 0);

    // 1) routing
    reset_kernel<<<1, 64>>>();
    gate_kernel<<<NTOK / 8, 256>>>(x, gw, gb);
    scan_kernel<<<1, 32>>>();
    scatter_kernel<<<NTOK / 256, 256>>>();

    // 2) UP: merged persistent GEMM with fused SwiGLU epilogue
    //    shared segment: x @ sgw -> S_sh (swiglu applied)
    //    routed segment: gather(x) @ egw[e] -> S_rt (w * swiglu applied)
    gemm_moe<true><<<nsm, 256>>>(0,
        x, CDIM, sgw, 2 * HSH, pS_sh, HSH, CDIM, NTOK / BM, 2 * HSH / BN,
        x, CDIM, egw, (long)CDIM * 2 * HEXP, 2 * HEXP,
        pS_rt, HEXP, CDIM, 2 * HEXP / BN, pTokOfRow, pWrow);

    // 3) DOWN: merged persistent GEMM (plain epilogue)
    gemm_moe<false><<<nsm, 256>>>(1,
        pS_sh, HSH, sdw, CDIM, out, CDIM, HSH, NTOK / BM, CDIM / BN,
        pS_rt, HEXP, edw, (long)HEXP * CDIM, CDIM,
        pR, CDIM, HEXP, CDIM / BN, nullptr, nullptr);

    // 4) combine
    combine_kernel<<<NTOK, 256>>>(out);
}

// round 17
// speedup vs baseline: 4.1523x; 1.0056x over previous
#include <cuda_runtime.h>
#include <cuda_fp16.h>
#include <math.h>

// Problem constants
#define NTOK 2048
#define CDIM 1024
#define NEXP 32
#define KSEL 4
#define HEXP 512
#define HSH  1024
#define NROW (NTOK * KSEL)   // 8192 grouped rows

#define BM 128
#define BN 256
#define KT 32    // k floats per chunk
#define KP 16    // half2 pairs per chunk
#define MTMAX (NTOK / BM)    // max m-tiles per expert (16)

// ---------------------------------------------------------------------------
// Static device scratch (no allocation allowed)
// ---------------------------------------------------------------------------
__device__ float g_S_sh[(size_t)NTOK * HSH];       // shared swiglu activation
__device__ float g_S_rt[(size_t)NROW * HEXP];      // routed swiglu activation (pre-scaled)
__device__ float g_R[(size_t)NROW * CDIM];         // routed down-proj output (grouped)

__device__ int   g_topk_idx[NROW];
__device__ float g_topk_w[NROW];
__device__ int   g_counts[NEXP];
__device__ int   g_offsets[NEXP + 1];
__device__ int   g_cursor[NEXP];
__device__ int   g_mtile_base[NEXP + 1];   // cumulative M-tiles per expert
__device__ int   g_tile_ctr;               // dynamic tile counter
__device__ int   g_done_sh[MTMAX];                 // UP-shared tiles done per m-tile
__device__ int   g_done_rt[NEXP * MTMAX];          // UP-routed tiles done per (e, mtl)
__device__ int   g_tok_of_row[NROW];
__device__ float g_w_of_row[NROW];
__device__ int   g_rows_of_token[NROW];

// ---------------------------------------------------------------------------
// Gating: one warp per token, lane = expert (E == 32)
// ---------------------------------------------------------------------------
__global__ void gate_kernel(const float* __restrict__ x,
                            const float* __restrict__ gw,
                            const float* __restrict__ gb)
{
    const int warp = threadIdx.x >> 5;
    const int lane = threadIdx.x & 31;
    const int n = blockIdx.x * 8 + warp;
    if (n >= NTOK) return;

    const float* xr = x + (size_t)n * CDIM;
    float acc = 0.f;
    #pragma unroll 2
    for (int c = 0; c < CDIM; c += 4) {
        const float4 xv = *(const float4*)(xr + c);
        acc += xv.x * gw[(c + 0) * NEXP + lane]
             + xv.y * gw[(c + 1) * NEXP + lane]
             + xv.z * gw[(c + 2) * NEXP + lane]
             + xv.w * gw[(c + 3) * NEXP + lane];
    }

    const float score  = 1.f / (1.f + expf(-acc));
    float mb = score + gb[lane];

    float wsum = 0.f;
    int   myIdx = 0;
    float myS   = 0.f;
    const float NEG_INF = __int_as_float(0xff800000);

    #pragma unroll
    for (int k = 0; k < KSEL; ++k) {
        float v = mb; int bi = lane;
        #pragma unroll
        for (int off = 16; off; off >>= 1) {
            float ov = __shfl_xor_sync(0xffffffffu, v, off);
            int   oi = __shfl_xor_sync(0xffffffffu, bi, off);
            if (ov > v || (ov == v && oi < bi)) { v = ov; bi = oi; }
        }
        float s = __shfl_sync(0xffffffffu, score, bi);
        wsum += s;
        if (lane == k)  { myIdx = bi; myS = s; }
        if (lane == bi) mb = NEG_INF;
    }

    if (lane < KSEL) {
        g_topk_idx[n * KSEL + lane] = myIdx;
        g_topk_w[n * KSEL + lane]   = myS / wsum;   // ROUTE_SCALE = 1.0
        atomicAdd(&g_counts[myIdx], 1);
    }
}

__global__ void reset_kernel()   // <<<2,256>>>
{
    const int idx = blockIdx.x * 256 + threadIdx.x;
    if (idx < NEXP) g_counts[idx] = 0;
    if (idx < MTMAX) g_done_sh[idx] = 0;
    if (idx < NEXP * MTMAX) g_done_rt[idx] = 0;
}

__global__ void scan_kernel()
{
    if (threadIdx.x == 0) {
        int acc = 0, mt = 0;
        for (int e = 0; e < NEXP; ++e) {
            g_offsets[e] = acc;
            g_cursor[e]  = acc;
            g_mtile_base[e] = mt;
            const int cnt = g_counts[e];
            acc += cnt;
            mt  += (cnt + BM - 1) / BM;
        }
        g_offsets[NEXP] = acc;     // == NROW
        g_mtile_base[NEXP] = mt;
        g_tile_ctr = 0;
    }
}

__global__ void scatter_kernel()
{
    const int n = blockIdx.x * blockDim.x + threadIdx.x;
    if (n >= NTOK) return;
    #pragma unroll
    for (int k = 0; k < KSEL; ++k) {
        const int e = g_topk_idx[n * KSEL + k];
        const int pos = atomicAdd(&g_cursor[e], 1);
        g_tok_of_row[pos] = n;
        g_w_of_row[pos]   = g_topk_w[n * KSEL + k];
        g_rows_of_token[n * KSEL + k] = pos;
    }
}

// ---------------------------------------------------------------------------
// FP16 tensor-core GEMM tile (fp32 accumulate), double-buffered, XOR-swizzled.
// Tile 128(M) x 256(N) x 32(K chunk), 256 threads = 8 warps (2x4), warp 64x64.
// FUSE=true: interleaved-B load + fused SwiGLU epilogue (no U roundtrip).
// ---------------------------------------------------------------------------
struct SmemT {
    unsigned As[2][KP][BM];   // 16 KB (half2 pairs, [kp][m^swz])
    unsigned Bs[2][KP][BN];   // 32 KB (half2 pairs, [kp][n^swz])
};

__device__ __forceinline__ unsigned pack_h2(float lo, float hi)
{
    __half2 h = __floats2half2_rn(lo, hi);
    return *(unsigned*)&h;
}

__device__ __forceinline__ void mma_f16(float* c, const unsigned* a, const unsigned* b)
{
    asm volatile(
        "mma.sync.aligned.m16n8k16.row.col.f32.f16.f16.f32 "
        "{%0,%1,%2,%3}, {%4,%5,%6,%7}, {%8,%9}, {%0,%1,%2,%3};"
        : "+f"(c[0]), "+f"(c[1]), "+f"(c[2]), "+f"(c[3])
        : "r"(a[0]), "r"(a[1]), "r"(a[2]), "r"(a[3]),
          "r"(b[0]), "r"(b[1]));
}

__device__ __forceinline__ float silu_f(float g) { return g / (1.f + expf(-g)); }

template<bool FUSE>
__device__ __forceinline__ void run_tile(SmemT& SMEM,
    const float* __restrict__ A, int lda,
    const float* __restrict__ Bp, int ldb,
    float* __restrict__ Cbase, int ldc, int Kd,
    int rowBase, int Me, int tileM, int tileN,
    const int* __restrict__ gather,
    const float* __restrict__ wrow)     // per-row scale (FUSE routed) or null
{
    const int tid  = threadIdx.x;
    const int wid  = tid >> 5;
    const int lane = tid & 31;
    const int g    = lane >> 2;        // 0..7
    const int tg   = lane & 3;         // 0..3
    const int wm   = (wid & 1) * 64;   // warp m-offset
    const int wn   = (wid >> 1) * 64;  // warp n-offset
    const int swz  = tg * 8;           // fragment-read swizzle offset

    // ---- A loader: one m-row per thread, 16 consecutive k floats
    const int am  = tid & 127;
    const int kh  = (tid >> 7) * 16;   // 0 or 16
    const int kp0a = kh >> 1;          // 0 or 8
    const bool av = (tileM + am) < Me;
    int arow = 0;
    if (av) {
        const int gr = rowBase + tileM + am;
        arow = gather ? gather[gr] : gr;
    }
    const float* apt = A + (size_t)arow * lda + kh;

    // ---- B loader: 4 kp rows x 4 phys n-cols per thread
    const int n4  = (tid & 63) * 4;    // 0..252 (phys col)
    const int kp0 = tid >> 6;          // 0..3
    const float* bpt = Bp + (size_t)(2 * kp0) * ldb + tileN + n4;
    const int hc = (tileN + n4) >> 1;  // logical y/g column (FUSE)
    const float* byp = Bp + (size_t)(2 * kp0) * ldb + hc;
    const float* bgp = byp + (ldb >> 1);

    float aLoad[16];
    float4 b0r[4], b1r[4];
    const float4 zf4 = make_float4(0.f, 0.f, 0.f, 0.f);

    // ---- prologue: load tile 0
    #pragma unroll
    for (int j = 0; j < 4; ++j)
        *(float4*)&aLoad[j * 4] = av ? *(const float4*)(apt + j * 4) : zf4;
    #pragma unroll
    for (int i = 0; i < 4; ++i) {
        if (FUSE) {
            const float2 y0 = *(const float2*)(byp + (size_t)(8 * i) * ldb);
            const float2 g0 = *(const float2*)(bgp + (size_t)(8 * i) * ldb);
            const float2 y1 = *(const float2*)(byp + (size_t)(8 * i + 1) * ldb);
            const float2 g1 = *(const float2*)(bgp + (size_t)(8 * i + 1) * ldb);
            b0r[i] = make_float4(y0.x, g0.x, y0.y, g0.y);
            b1r[i] = make_float4(y1.x, g1.x, y1.y, g1.y);
        } else {
            b0r[i] = *(const float4*)(bpt + (size_t)(8 * i) * ldb);
            b1r[i] = *(const float4*)(bpt + (size_t)(8 * i + 1) * ldb);
        }
    }

    // ---- store tile 0 into buffer 0
    #pragma unroll
    for (int j = 0; j < 8; ++j) {
        const int kp = kp0a + j;
        SMEM.As[0][kp][am ^ (8 * (kp & 3))] = pack_h2(aLoad[2 * j], aLoad[2 * j + 1]);
    }
    #pragma unroll
    for (int i = 0; i < 4; ++i) {
        const int kp = kp0 + 4 * i;
        uint4 u;
        u.x = pack_h2(b0r[i].x, b1r[i].x);
        u.y = pack_h2(b0r[i].y, b1r[i].y);
        u.z = pack_h2(b0r[i].z, b1r[i].z);
        u.w = pack_h2(b0r[i].w, b1r[i].w);
        *(uint4*)&SMEM.Bs[0][kp][n4 ^ (8 * (kp & 3))] = u;
    }
    __syncthreads();

    float acc[4][8][4];
    #pragma unroll
    for (int mf = 0; mf < 4; ++mf)
        #pragma unroll
        for (int nf = 0; nf < 8; ++nf)
            #pragma unroll
            for (int r = 0; r < 4; ++r)
                acc[mf][nf][r] = 0.f;

    int buf = 0;
    for (int k0 = 0; k0 < Kd; k0 += KT) {
        const bool hasNext = (k0 + KT) < Kd;

        if (hasNext) {
            const float* ap2 = apt + k0 + KT;
            #pragma unroll
            for (int j = 0; j < 4; ++j)
                *(float4*)&aLoad[j * 4] = av ? *(const float4*)(ap2 + j * 4) : zf4;
            #pragma unroll
            for (int i = 0; i < 4; ++i) {
                if (FUSE) {
                    const float* by2 = byp + (size_t)(k0 + KT) * ldb;
                    const float* bg2 = bgp + (size_t)(k0 + KT) * ldb;
                    const float2 y0 = *(const float2*)(by2 + (size_t)(8 * i) * ldb);
                    const float2 g0 = *(const float2*)(bg2 + (size_t)(8 * i) * ldb);
                    const float2 y1 = *(const float2*)(by2 + (size_t)(8 * i + 1) * ldb);
                    const float2 g1 = *(const float2*)(bg2 + (size_t)(8 * i + 1) * ldb);
                    b0r[i] = make_float4(y0.x, g0.x, y0.y, g0.y);
                    b1r[i] = make_float4(y1.x, g1.x, y1.y, g1.y);
                } else {
                    const float* bp2 = bpt + (size_t)(k0 + KT) * ldb;
                    b0r[i] = *(const float4*)(bp2 + (size_t)(8 * i) * ldb);
                    b1r[i] = *(const float4*)(bp2 + (size_t)(8 * i + 1) * ldb);
                }
            }
        }

        #pragma unroll
        for (int s = 0; s < 2; ++s) {
            const int kb = s * 8;
            unsigned a[4][4], b[8][2];
            #pragma unroll
            for (int mf = 0; mf < 4; ++mf) {
                const int m = wm + mf * 16 + g;
                a[mf][0] = SMEM.As[buf][kb + tg    ][ m      ^ swz];
                a[mf][1] = SMEM.As[buf][kb + tg    ][(m + 8) ^ swz];
                a[mf][2] = SMEM.As[buf][kb + tg + 4][ m      ^ swz];   // (tg+4)&3 == tg
                a[mf][3] = SMEM.As[buf][kb + tg + 4][(m + 8) ^ swz];
            }
            #pragma unroll
            for (int nf = 0; nf < 8; ++nf) {
                const int n = wn + nf * 8 + g;
                b[nf][0] = SMEM.Bs[buf][kb + tg    ][n ^ swz];
                b[nf][1] = SMEM.Bs[buf][kb + tg + 4][n ^ swz];
            }
            #pragma unroll
            for (int mf = 0; mf < 4; ++mf)
                #pragma unroll
                for (int nf = 0; nf < 8; ++nf)
                    mma_f16(acc[mf][nf], a[mf], b[nf]);
        }

        if (hasNext) {
            const int nb = buf ^ 1;
            #pragma unroll
            for (int j = 0; j < 8; ++j) {
                const int kp = kp0a + j;
                SMEM.As[nb][kp][am ^ (8 * (kp & 3))] = pack_h2(aLoad[2 * j], aLoad[2 * j + 1]);
            }
            #pragma unroll
            for (int i = 0; i < 4; ++i) {
                const int kp = kp0 + 4 * i;
                uint4 u;
                u.x = pack_h2(b0r[i].x, b1r[i].x);
                u.y = pack_h2(b0r[i].y, b1r[i].y);
                u.z = pack_h2(b0r[i].z, b1r[i].z);
                u.w = pack_h2(b0r[i].w, b1r[i].w);
                *(uint4*)&SMEM.Bs[nb][kp][n4 ^ (8 * (kp & 3))] = u;
            }
        }
        __syncthreads();
        buf ^= 1;
    }

    // ---- Epilogue
    if (FUSE) {
        #pragma unroll
        for (int mf = 0; mf < 4; ++mf) {
            const int r0 = tileM + wm + mf * 16 + g;
            const int r1 = r0 + 8;
            float w0 = 1.f, w1 = 1.f;
            if (wrow) {
                if (r0 < Me) w0 = wrow[rowBase + r0];
                if (r1 < Me) w1 = wrow[rowBase + r1];
            }
            #pragma unroll
            for (int nf = 0; nf < 8; ++nf) {
                const int pc = wn + nf * 8 + tg * 2;
                const int oc = (tileN + pc) >> 1;
                if (r0 < Me)
                    Cbase[(size_t)(rowBase + r0) * ldc + oc] =
                        w0 * acc[mf][nf][0] * silu_f(acc[mf][nf][1]);
                if (r1 < Me)
                    Cbase[(size_t)(rowBase + r1) * ldc + oc] =
                        w1 * acc[mf][nf][2] * silu_f(acc[mf][nf][3]);
            }
        }
    } else {
        #pragma unroll
        for (int mf = 0; mf < 4; ++mf) {
            const int r0 = tileM + wm + mf * 16 + g;
            const int r1 = r0 + 8;
            #pragma unroll
            for (int nf = 0; nf < 8; ++nf) {
                const int col = tileN + wn + nf * 8 + tg * 2;
                if (r0 < Me)
                    *(float2*)&Cbase[(size_t)(rowBase + r0) * ldc + col] =
                        make_float2(acc[mf][nf][0], acc[mf][nf][1]);
                if (r1 < Me)
                    *(float2*)&Cbase[(size_t)(rowBase + r1) * ldc + col] =
                        make_float2(acc[mf][nf][2], acc[mf][nf][3]);
            }
        }
    }
}

// ---------------------------------------------------------------------------
// Dependency signal / wait (cross-SM, within one launch)
// ---------------------------------------------------------------------------
__device__ __forceinline__ void dep_signal(int* ctr)
{
    __threadfence();          // each thread's C stores visible at GPU scope
    __syncthreads();          // all threads' fences done before the atomic
    if (threadIdx.x == 0) atomicAdd(ctr, 1);
}

__device__ __forceinline__ void dep_wait(int* ctr, int need)
{
    if (threadIdx.x == 0) {
        while (atomicAdd(ctr, 0) < need) __nanosleep(200);
        __threadfence();
    }
    __syncthreads();
}

// ---------------------------------------------------------------------------
// Single persistent fused GEMM: [UP-shared | UP-routed | DOWN-shared | DOWN-routed]
// with device-side dependency tracking between UP and DOWN tiles.
// ---------------------------------------------------------------------------
__global__ __launch_bounds__(256)
void gemm_all(const float* __restrict__ x,
              const float* __restrict__ sgw, const float* __restrict__ egw,
              const float* __restrict__ sdw, const float* __restrict__ edw,
              float* __restrict__ S_sh, float* __restrict__ S_rt,
              float* __restrict__ R, float* __restrict__ out,
              const int* __restrict__ gather, const float* __restrict__ wrow)
{
    __shared__ SmemT SMEM;
    __shared__ int s_t;
    __shared__ int s_mtb[NEXP + 1];
    __shared__ int s_off[NEXP + 1];

    if (threadIdx.x <= NEXP) {
        s_mtb[threadIdx.x] = g_mtile_base[threadIdx.x];
        s_off[threadIdx.x] = g_offsets[threadIdx.x];
    }
    __syncthreads();

    const int MT    = s_mtb[NEXP];
    const int T_us  = (NTOK / BM) * (2 * HSH / BN);   // 128 UP-shared
    const int T_ur  = MT * (2 * HEXP / BN);           // UP-routed (MT*4)
    const int T_ds  = (NTOK / BM) * (CDIM / BN);      // 64 DOWN-shared
    const int T_dr  = MT * (CDIM / BN);               // DOWN-routed (MT*4)
    const int T     = T_us + T_ur + T_ds + T_dr;

    for (;;) {
        if (threadIdx.x == 0) s_t = atomicAdd(&g_tile_ctr, 1);
        __syncthreads();
        const int t = s_t;
        __syncthreads();
        if (t >= T) break;

        if (t < T_us) {
            // ---- UP shared: x @ sgw -> S_sh (fused swiglu)
            const int mt = t >> 3, nt = t & 7;
            run_tile<true>(SMEM, x, CDIM, sgw, 2 * HSH, S_sh, HSH, CDIM,
                           0, NTOK, mt * BM, nt * BN, nullptr, nullptr);
            dep_signal(&g_done_sh[mt]);
        } else if (t < T_us + T_ur) {
            // ---- UP routed: gather(x) @ egw[e] -> S_rt (w * fused swiglu)
            const int tt = t - T_us;
            const int mt = tt >> 2, nt = tt & 3;
            int e = 0;
            while (s_mtb[e + 1] <= mt) ++e;
            const int mtl = mt - s_mtb[e];
            run_tile<true>(SMEM, x, CDIM, egw + (size_t)e * CDIM * 2 * HEXP, 2 * HEXP,
                           S_rt, HEXP, CDIM,
                           s_off[e], s_off[e + 1] - s_off[e],
                           mtl * BM, nt * BN, gather, wrow);
            dep_signal(&g_done_rt[e * MTMAX + mtl]);
        } else if (t < T_us + T_ur + T_ds) {
            // ---- DOWN shared: S_sh @ sdw -> out
            const int tt = t - T_us - T_ur;
            const int mt = tt >> 2, nt = tt & 3;
            dep_wait(&g_done_sh[mt], 2 * HSH / BN);
            run_tile<false>(SMEM, S_sh, HSH, sdw, CDIM, out, CDIM, HSH,
                            0, NTOK, mt * BM, nt * BN, nullptr, nullptr);
        } else {
            // ---- DOWN routed: S_rt @ edw[e] -> R
            const int tt = t - T_us - T_ur - T_ds;
            const int mt = tt >> 2, nt = tt & 3;
            int e = 0;
            while (s_mtb[e + 1] <= mt) ++e;
            const int mtl = mt - s_mtb[e];
            dep_wait(&g_done_rt[e * MTMAX + mtl], 2 * HEXP / BN);
            run_tile<false>(SMEM, S_rt, HEXP, edw + (size_t)e * HEXP * CDIM, CDIM,
                            R, CDIM, HEXP,
                            s_off[e], s_off[e + 1] - s_off[e],
                            mtl * BM, nt * BN, nullptr, nullptr);
        }
    }
}

// out[n] = shared(already in out) + sum_k R[rows_of_token[n][k]]
__global__ void combine_kernel(float* __restrict__ out)  // grid = NTOK, 256 threads
{
    const int n = blockIdx.x;
    const int t = threadIdx.x;
    const int r0 = g_rows_of_token[n * KSEL + 0];
    const int r1 = g_rows_of_token[n * KSEL + 1];
    const int r2 = g_rows_of_token[n * KSEL + 2];
    const int r3 = g_rows_of_token[n * KSEL + 3];

    float4 o  = *(float4*)&out[(size_t)n * CDIM + t * 4];
    const float4 a = *(const float4*)&g_R[(size_t)r0 * CDIM + t * 4];
    const float4 b = *(const float4*)&g_R[(size_t)r1 * CDIM + t * 4];
    const float4 c = *(const float4*)&g_R[(size_t)r2 * CDIM + t * 4];
    const float4 d = *(const float4*)&g_R[(size_t)r3 * CDIM + t * 4];
    o.x += a.x + b.x + c.x + d.x;
    o.y += a.y + b.y + c.y + d.y;
    o.z += a.z + b.z + c.z + d.z;
    o.w += a.w + b.w + c.w + d.w;
    *(float4*)&out[(size_t)n * CDIM + t * 4] = o;
}

// ---------------------------------------------------------------------------
// Launch
// ---------------------------------------------------------------------------
extern "C" void kernel_launch(void* const* d_in, const int* in_sizes, int n_in,
                              void* d_out, int out_size)
{
    (void)in_sizes; (void)n_in; (void)out_size;
    const float* x   = (const float*)d_in[0];   // (1,2048,1024)
    const float* gw  = (const float*)d_in[1];   // (1024,32)
    const float* gb  = (const float*)d_in[2];   // (32,)
    const float* sgw = (const float*)d_in[3];   // (1024,2048)
    const float* sdw = (const float*)d_in[4];   // (1024,1024)
    const float* egw = (const float*)d_in[5];   // (32,1024,1024)
    const float* edw = (const float*)d_in[6];   // (32,512,1024)
    float* out = (float*)d_out;

    // Resolve device-scratch addresses (no allocation, capture-safe)
    float *pS_sh, *pS_rt, *pR, *pWrow;
    int *pTokOfRow;
    cudaGetSymbolAddress((void**)&pS_sh, g_S_sh);
    cudaGetSymbolAddress((void**)&pS_rt, g_S_rt);
    cudaGetSymbolAddress((void**)&pR,    g_R);
    cudaGetSymbolAddress((void**)&pWrow, g_w_of_row);
    cudaGetSymbolAddress((void**)&pTokOfRow, g_tok_of_row);

    int nsm = 148;
    cudaDeviceGetAttribute(&nsm, cudaDevAttrMultiProcessorCount, 0);

    // 1) routing
    reset_kernel<<<2, 256>>>();
    gate_kernel<<<NTOK / 8, 256>>>(x, gw, gb);
    scan_kernel<<<1, 32>>>();
    scatter_kernel<<<NTOK / 256, 256>>>();

    // 2) one persistent fused GEMM launch (UP + DOWN with device-side deps)
    gemm_all<<<nsm, 256>>>(x, sgw, egw, sdw, edw,
                           pS_sh, pS_rt, pR, out, pTokOfRow, pWrow);

    // 3) combine
    combine_kernel<<<NTOK, 256>>>(out);
}